// round 13
// baseline (speedup 1.0000x reference)
#include <cuda_runtime.h>
#include <cuda_fp16.h>
#include <math.h>

#define NN 100000
#define EE 800000
#define ET (EE + NN)
#define GG 128
#define NB 98   /* ceil(NN/1024) */
#define FULL 0xffffffffu
#define LOG2E 1.4426950408889634f

typedef unsigned long long ull;

// ---------------- scratch (static device memory) ----------------
__device__ __half d_hh[(size_t)NN * 256];    // h fp16 (51 MB, L2-resident)
__device__ __half d_o1h[(size_t)NN * 128];   // out1 fp16
__device__ __half d_o2h[(size_t)NN * 128];   // out2 fp16
__device__ float d_als[NN * 2], d_ald[NN * 2];   // pre-scaled by log2(e)
__device__ float d_eg[NN];
__device__ float d_gs[GG];
__device__ float d_pooled[GG * 128];
__device__ float d_T1[50 * 256];
__device__ unsigned d_W2p[8 * 32 * 32 * 2];  // prepacked B frags
__device__ unsigned d_gw1p[8 * 16 * 32 * 2];
__device__ float d_gA[128], d_gB[128];       // folded BN for gate
__device__ int d_deg[NN], d_incl[NN], d_ptr[NN + 1], d_pos[NN];
__device__ int d_srcs[ET];
__device__ int d_bsum[128];
__device__ int d_i64;

__constant__ int c_voff[6] = {0, 33, 38, 41, 45, 47};

// ---------------- helpers ----------------
__device__ __forceinline__ float sig_(float x) { return 1.f / (1.f + __expf(-x)); }
__device__ __forceinline__ float ex2_(float x) {
    float r;
    asm("ex2.approx.ftz.f32 %0, %1;" : "=f"(r) : "f"(x));
    return r;
}
__device__ __forceinline__ float warpSum(float v) {
#pragma unroll
    for (int o = 16; o; o >>= 1) v += __shfl_xor_sync(FULL, v, o);
    return v;
}
__device__ __forceinline__ int warpSumI(int v) {
#pragma unroll
    for (int o = 16; o; o >>= 1) v += __shfl_xor_sync(FULL, v, o);
    return v;
}
__device__ __forceinline__ float dot4(float4 a, float4 b) {
    return a.x * b.x + a.y * b.y + a.z * b.z + a.w * b.w;
}
__device__ __forceinline__ int gi(const int* __restrict__ p, int i, int m64) {
    return p[m64 ? (i << 1) : i];
}
__device__ __forceinline__ unsigned h2u(__half2 h) { return *(unsigned*)&h; }

// ---------------- prep ----------------
__global__ void k_prep(const int* __restrict__ ei) {
    int i = blockIdx.x * blockDim.x + threadIdx.x;
    if (i == 0)
        d_i64 = ((ei[1] | ei[3] | ei[5] | ei[7] | ei[9]) == 0) ? 1 : 0;
    if (i < NN) d_deg[i] = 1;
    if (i < GG * 128) d_pooled[i] = 0.f;
    if (i < GG) d_gs[i] = 0.f;
}

// ---------------- pack W2/gw1 frags + fold BN constants ----------------
__global__ void k_pack(const float* __restrict__ W2, const float* __restrict__ gw1,
                       const float* __restrict__ gb1,
                       const float* __restrict__ bng, const float* __restrict__ bnb,
                       const float* __restrict__ bnm, const float* __restrict__ bnv) {
    int t = blockIdx.x * blockDim.x + threadIdx.x;
    if (t < 8192) {
        int lane = t & 31, nt = (t >> 5) & 31, kk = t >> 10;
        int k0 = kk * 16 + (lane & 3) * 2, n = nt * 8 + (lane >> 2);
        unsigned lo = h2u(__float22half2_rn(make_float2(W2[k0 * 256 + n],       W2[(k0 + 1) * 256 + n])));
        unsigned hi = h2u(__float22half2_rn(make_float2(W2[(k0 + 8) * 256 + n], W2[(k0 + 9) * 256 + n])));
        d_W2p[t * 2] = lo; d_W2p[t * 2 + 1] = hi;
    } else if (t < 8192 + 4096) {
        int u = t - 8192;
        int lane = u & 31, nt = (u >> 5) & 15, kk = u >> 9;
        int k0 = kk * 16 + (lane & 3) * 2, n = nt * 8 + (lane >> 2);
        unsigned lo = h2u(__float22half2_rn(make_float2(gw1[k0 * 128 + n],       gw1[(k0 + 1) * 128 + n])));
        unsigned hi = h2u(__float22half2_rn(make_float2(gw1[(k0 + 8) * 128 + n], gw1[(k0 + 9) * 128 + n])));
        d_gw1p[u * 2] = lo; d_gw1p[u * 2 + 1] = hi;
    } else if (t < 8192 + 4096 + 128) {
        int j = t - 8192 - 4096;
        float a = rsqrtf(bnv[j] + 1e-5f) * bng[j];
        d_gA[j] = a;
        d_gB[j] = (gb1[j] - bnm[j]) * a + bnb[j];
    }
}

// ---------------- T1 = emb_i @ W1_i ----------------
__global__ void k_T1(const float* __restrict__ e0, const float* __restrict__ e1,
                     const float* __restrict__ e2, const float* __restrict__ e3,
                     const float* __restrict__ e4, const float* __restrict__ e5,
                     const float* __restrict__ W1) {
    int row = blockIdx.x;
    int j = threadIdx.x;
    int i, v;
    if (row < 33)      { i = 0; v = row; }
    else if (row < 38) { i = 1; v = row - 33; }
    else if (row < 41) { i = 2; v = row - 38; }
    else if (row < 45) { i = 3; v = row - 41; }
    else if (row < 47) { i = 4; v = row - 45; }
    else               { i = 5; v = row - 47; }
    const float* emb = (i == 0) ? e0 : (i == 1) ? e1 : (i == 2) ? e2 : (i == 3) ? e3 : (i == 4) ? e4 : e5;
    float acc = 0.f;
#pragma unroll 8
    for (int c = 0; c < 64; c++) acc = fmaf(emb[v * 64 + c], W1[(size_t)(i * 64 + c) * 256 + j], acc);
    d_T1[row * 256 + j] = acc;
}

// ---------------- h1 embed + fused attention logits ----------------
__global__ void k_embed(const int* __restrict__ x,
                        const float* __restrict__ as_, const float* __restrict__ ad_) {
    int n = blockIdx.x * 8 + (threadIdx.x >> 5);
    int lane = threadIdx.x & 31;
    if (n >= NN) return;
    int m64 = d_i64;
    int xv = 0;
    if (lane < 6) xv = gi(x, n * 6 + lane, m64);
    int rows[6];
#pragma unroll
    for (int i = 0; i < 6; i++) rows[i] = c_voff[i] + __shfl_sync(FULL, xv, i);
    float4 a0 = make_float4(0.f, 0.f, 0.f, 0.f), a1 = make_float4(0.f, 0.f, 0.f, 0.f);
#pragma unroll
    for (int i = 0; i < 6; i++) {
        const float4* T = (const float4*)(d_T1 + rows[i] * 256);
        float4 t0 = T[lane], t1 = T[lane + 32];
        a0.x += t0.x; a0.y += t0.y; a0.z += t0.z; a0.w += t0.w;
        a1.x += t1.x; a1.y += t1.y; a1.z += t1.z; a1.w += t1.w;
    }
    uint2 u0, u1;
    u0.x = h2u(__float22half2_rn(make_float2(a0.x, a0.y)));
    u0.y = h2u(__float22half2_rn(make_float2(a0.z, a0.w)));
    u1.x = h2u(__float22half2_rn(make_float2(a1.x, a1.y)));
    u1.y = h2u(__float22half2_rn(make_float2(a1.z, a1.w)));
    *(uint2*)(d_hh + (size_t)n * 256 + 4 * lane) = u0;
    *(uint2*)(d_hh + (size_t)n * 256 + 128 + 4 * lane) = u1;
    float4 s0 = __ldg((const float4*)as_ + lane), s1 = __ldg((const float4*)as_ + lane + 32);
    float4 t0 = __ldg((const float4*)ad_ + lane), t1 = __ldg((const float4*)ad_ + lane + 32);
    float ps0 = warpSum(dot4(a0, s0));
    float ps1 = warpSum(dot4(a1, s1));
    float pd0 = warpSum(dot4(a0, t0));
    float pd1 = warpSum(dot4(a1, t1));
    if (lane == 0) {
        d_als[n * 2] = ps0 * LOG2E; d_als[n * 2 + 1] = ps1 * LOG2E;
        d_ald[n * 2] = pd0 * LOG2E; d_ald[n * 2 + 1] = pd1 * LOG2E;
    }
}

// ---------------- CSR build ----------------
__global__ void k_hist(const int* __restrict__ ei) {
    int t = blockIdx.x * blockDim.x + threadIdx.x;
    if (t < EE) atomicAdd(&d_deg[gi(ei, EE + t, d_i64)], 1);
}
__global__ void k_scan1() {
    __shared__ int ws[32];
    int i = blockIdx.x * 1024 + threadIdx.x;
    int lane = threadIdx.x & 31, w = threadIdx.x >> 5;
    int x = (i < NN) ? d_deg[i] : 0;
#pragma unroll
    for (int o = 1; o < 32; o <<= 1) { int y = __shfl_up_sync(FULL, x, o); if (lane >= o) x += y; }
    if (lane == 31) ws[w] = x;
    __syncthreads();
    if (w == 0) {
        int t = ws[lane];
#pragma unroll
        for (int o = 1; o < 32; o <<= 1) { int y = __shfl_up_sync(FULL, t, o); if (lane >= o) t += y; }
        ws[lane] = t;
    }
    __syncthreads();
    x += (w > 0) ? ws[w - 1] : 0;
    if (i < NN) d_incl[i] = x;
    if (threadIdx.x == 1023) d_bsum[blockIdx.x] = x;
}
__global__ void k_scan23() {
    __shared__ int off_s;
    int tid = threadIdx.x;
    if (tid < 32) {
        int v = 0;
        for (int b = tid; b < blockIdx.x; b += 32) v += d_bsum[b];
        v = warpSumI(v);
        if (tid == 0) off_s = v;
    }
    __syncthreads();
    int i = blockIdx.x * 1024 + tid;
    if (i < NN) {
        int e = d_incl[i] - d_deg[i] + off_s;
        d_ptr[i] = e;
        d_pos[i] = e;
    }
    if (i == 0) d_ptr[NN] = ET;
}
__global__ void k_scatter(const int* __restrict__ ei) {
    int t = blockIdx.x * blockDim.x + threadIdx.x;
    if (t >= ET) return;
    int m64 = d_i64;
    int s, d;
    if (t < EE) { s = gi(ei, t, m64); d = gi(ei, EE + t, m64); }
    else { s = d = t - EE; }
    d_srcs[atomicAdd(&d_pos[d], 1)] = s;
}

// ---------------- HMMA layer-2 GEMM + fused als/ald ----------------
__global__ void k_hmma2(const __half* __restrict__ A, const unsigned* __restrict__ Bp,
                        const float* __restrict__ as_, const float* __restrict__ ad_, int M) {
    constexpr int NT = 32, NTW = 16;
    __shared__ __half As[64 * 136];
    int tid = threadIdx.x;
    int wid = tid >> 5, lane = tid & 31;
    int wm = wid >> 1, wn = wid & 1;
    int row0 = blockIdx.x * 64;

    {
        const uint4* Ag = (const uint4*)(A + (size_t)row0 * 128);
        uint4* Asm = (uint4*)As;
#pragma unroll
        for (int u = 0; u < 4; u++) {
            int f = tid + 256 * u;
            int r = f >> 4, c4 = f & 15;
            uint4 v = make_uint4(0, 0, 0, 0);
            if (row0 + r < M) v = __ldg(Ag + f);
            Asm[r * 17 + c4] = v;
        }
    }
    __syncthreads();

    float acc[NTW][4];
#pragma unroll
    for (int t = 0; t < NTW; t++) acc[t][0] = acc[t][1] = acc[t][2] = acc[t][3] = 0.f;
    int mrow = wm * 16;
    int arow = lane >> 2, acol = (lane & 3) * 2;
    const __half* Ab0 = As + (mrow + arow) * 136;
    const __half* Ab1 = As + (mrow + arow + 8) * 136;

#pragma unroll
    for (int kk = 0; kk < 8; kk++) {
        unsigned a0 = *(const unsigned*)(Ab0 + kk * 16 + acol);
        unsigned a1 = *(const unsigned*)(Ab1 + kk * 16 + acol);
        unsigned a2 = *(const unsigned*)(Ab0 + kk * 16 + acol + 8);
        unsigned a3 = *(const unsigned*)(Ab1 + kk * 16 + acol + 8);
#pragma unroll
        for (int t = 0; t < NTW; t++) {
            int nt = wn * NTW + t;
            uint2 b = __ldg((const uint2*)Bp + (kk * NT + nt) * 32 + lane);
            asm volatile(
                "mma.sync.aligned.m16n8k16.row.col.f32.f16.f16.f32 "
                "{%0,%1,%2,%3}, {%4,%5,%6,%7}, {%8,%9}, {%0,%1,%2,%3};"
                : "+f"(acc[t][0]), "+f"(acc[t][1]), "+f"(acc[t][2]), "+f"(acc[t][3])
                : "r"(a0), "r"(a1), "r"(a2), "r"(a3), "r"(b.x), "r"(b.y));
        }
    }

    int grow = row0 + mrow + arow;
    int coff = wn * 128 + (lane & 3) * 2;
    const float* S = as_ + wn * 128;
    const float* D = ad_ + wn * 128;
    float s0p = 0.f, d0p = 0.f, s1p = 0.f, d1p = 0.f;
#pragma unroll
    for (int t = 0; t < NTW; t++) {
        int lc = (lane & 3) * 2 + t * 8;
        float sa = __ldg(&S[lc]), sb = __ldg(&S[lc + 1]);
        float da = __ldg(&D[lc]), db = __ldg(&D[lc + 1]);
        s0p += acc[t][0] * sa + acc[t][1] * sb;
        d0p += acc[t][0] * da + acc[t][1] * db;
        s1p += acc[t][2] * sa + acc[t][3] * sb;
        d1p += acc[t][2] * da + acc[t][3] * db;
        int col = coff + t * 8;
        if (grow < M)
            *(__half2*)(d_hh + (size_t)grow * 256 + col) =
                __float22half2_rn(make_float2(acc[t][0], acc[t][1]));
        if (grow + 8 < M)
            *(__half2*)(d_hh + (size_t)(grow + 8) * 256 + col) =
                __float22half2_rn(make_float2(acc[t][2], acc[t][3]));
    }
#pragma unroll
    for (int o = 1; o < 4; o <<= 1) {
        s0p += __shfl_xor_sync(FULL, s0p, o);
        d0p += __shfl_xor_sync(FULL, d0p, o);
        s1p += __shfl_xor_sync(FULL, s1p, o);
        d1p += __shfl_xor_sync(FULL, d1p, o);
    }
    if ((lane & 3) == 0) {
        if (grow < M)     { d_als[grow * 2 + wn] = s0p * LOG2E;       d_ald[grow * 2 + wn] = d0p * LOG2E; }
        if (grow + 8 < M) { d_als[(grow + 8) * 2 + wn] = s1p * LOG2E; d_ald[(grow + 8) * 2 + wn] = d1p * LOG2E; }
    }
}

// ---------------- HMMA gate GEMM: fused BN+relu+dot(gw2)+exp+graph-sum ----------------
__global__ void k_hmmaG(const __half* __restrict__ A, const unsigned* __restrict__ Bp,
                        const float* __restrict__ gw2, const float* __restrict__ gb2,
                        const int* __restrict__ batch, int M) {
    constexpr int NT = 16, NTW = 8;
    __shared__ __half As[64 * 136];
    __shared__ float slog[64];
    int tid = threadIdx.x;
    int wid = tid >> 5, lane = tid & 31;
    int wm = wid >> 1, wn = wid & 1;
    int row0 = blockIdx.x * 64;

    if (tid < 64) slog[tid] = 0.f;
    {
        const uint4* Ag = (const uint4*)(A + (size_t)row0 * 128);
        uint4* Asm = (uint4*)As;
#pragma unroll
        for (int u = 0; u < 4; u++) {
            int f = tid + 256 * u;
            int r = f >> 4, c4 = f & 15;
            uint4 v = make_uint4(0, 0, 0, 0);
            if (row0 + r < M) v = __ldg(Ag + f);
            Asm[r * 17 + c4] = v;
        }
    }
    __syncthreads();

    float acc[NTW][4];
#pragma unroll
    for (int t = 0; t < NTW; t++) acc[t][0] = acc[t][1] = acc[t][2] = acc[t][3] = 0.f;
    int mrow = wm * 16;
    int arow = lane >> 2, acol = (lane & 3) * 2;
    const __half* Ab0 = As + (mrow + arow) * 136;
    const __half* Ab1 = As + (mrow + arow + 8) * 136;

#pragma unroll
    for (int kk = 0; kk < 8; kk++) {
        unsigned a0 = *(const unsigned*)(Ab0 + kk * 16 + acol);
        unsigned a1 = *(const unsigned*)(Ab1 + kk * 16 + acol);
        unsigned a2 = *(const unsigned*)(Ab0 + kk * 16 + acol + 8);
        unsigned a3 = *(const unsigned*)(Ab1 + kk * 16 + acol + 8);
#pragma unroll
        for (int t = 0; t < NTW; t++) {
            int nt = wn * NTW + t;
            uint2 b = __ldg((const uint2*)Bp + (kk * NT + nt) * 32 + lane);
            asm volatile(
                "mma.sync.aligned.m16n8k16.row.col.f32.f16.f16.f32 "
                "{%0,%1,%2,%3}, {%4,%5,%6,%7}, {%8,%9}, {%0,%1,%2,%3};"
                : "+f"(acc[t][0]), "+f"(acc[t][1]), "+f"(acc[t][2]), "+f"(acc[t][3])
                : "r"(a0), "r"(a1), "r"(a2), "r"(a3), "r"(b.x), "r"(b.y));
        }
    }

    float p0 = 0.f, p1 = 0.f;
#pragma unroll
    for (int t = 0; t < NTW; t++) {
        int c = wn * 64 + (lane & 3) * 2 + t * 8;
        float A0 = d_gA[c], A1 = d_gA[c + 1];
        float B0 = d_gB[c], B1 = d_gB[c + 1];
        float w0 = __ldg(&gw2[c]), w1 = __ldg(&gw2[c + 1]);
        float v;
        v = fmaf(acc[t][0], A0, B0); v = v > 0.f ? v : 0.f; p0 = fmaf(v, w0, p0);
        v = fmaf(acc[t][1], A1, B1); v = v > 0.f ? v : 0.f; p0 = fmaf(v, w1, p0);
        v = fmaf(acc[t][2], A0, B0); v = v > 0.f ? v : 0.f; p1 = fmaf(v, w0, p1);
        v = fmaf(acc[t][3], A1, B1); v = v > 0.f ? v : 0.f; p1 = fmaf(v, w1, p1);
    }
#pragma unroll
    for (int o = 1; o < 4; o <<= 1) {
        p0 += __shfl_xor_sync(FULL, p0, o);
        p1 += __shfl_xor_sync(FULL, p1, o);
    }
    int r0 = mrow + arow;
    if ((lane & 3) == 0) {
        atomicAdd(&slog[r0], p0);
        atomicAdd(&slog[r0 + 8], p1);
    }
    __syncthreads();
    if (tid < 64) {
        int n = row0 + tid;
        if (n < M) {
            float e = __expf(slog[tid] + __ldg(gb2));
            d_eg[n] = e;
            atomicAdd(&d_gs[gi(batch, n, d_i64)], e);
        }
    }
}

// ---------------- fused GAT: 2 warps per node, R11 pipeline per warp ----------------
__global__ void k_gat(const float* __restrict__ bias, __half* __restrict__ oh) {
    __shared__ float smA[4][32 * 9];   // odd-warp acc (padded stride 9)
    __shared__ float smS[4][2];        // odd-warp s0,s1
    int tid = threadIdx.x;
    int wid = tid >> 5, lane = tid & 31;
    int nb = wid >> 1, sub = wid & 1;
    int n = blockIdx.x * 4 + nb;
    int head = lane >> 4;
    const float2* ALS = (const float2*)d_als;

    float acc[8];
#pragma unroll
    for (int r = 0; r < 8; r++) acc[r] = 0.f;
    float s0 = 0.f, s1 = 0.f;
    float2 adv = make_float2(0.f, 0.f);

    if (n < NN) {
        adv = ((const float2*)d_ald)[n];
        int p0 = d_ptr[n], p1 = d_ptr[n + 1];
        int mid = p0 + ((p1 - p0 + 1) >> 1);
        int q0 = sub ? mid : p0;
        int q1 = sub ? p1 : mid;
        if (q0 < q1) {
            // 1-ahead software pipeline (exact R11 body)
            int sx = __ldg(&d_srcs[q0]);
            float2 a_n = __ldg(ALS + sx);
            uint4 q_n = __ldg((const uint4*)(d_hh + (size_t)sx * 256) + lane);
#pragma unroll 2
            for (int j = q0; j < q1; j++) {
                float2 a_c = a_n;
                uint4 q_c = q_n;
                int jn = j + 1;
                if (jn < q1) {
                    int sv = __ldg(&d_srcs[jn]);
                    a_n = __ldg(ALS + sv);
                    q_n = __ldg((const uint4*)(d_hh + (size_t)sv * 256) + lane);
                }
                float e0 = a_c.x + adv.x; e0 = e0 > 0.f ? e0 : 0.2f * e0;
                float e1 = a_c.y + adv.y; e1 = e1 > 0.f ? e1 : 0.2f * e1;
                float w0 = ex2_(e0), w1 = ex2_(e1);
                s0 += w0; s1 += w1;
                float w = head ? w1 : w0;
                __half2* hp = (__half2*)&q_c;
                float2 f0 = __half22float2(hp[0]), f1 = __half22float2(hp[1]);
                float2 f2 = __half22float2(hp[2]), f3 = __half22float2(hp[3]);
                acc[0] = fmaf(w, f0.x, acc[0]); acc[1] = fmaf(w, f0.y, acc[1]);
                acc[2] = fmaf(w, f1.x, acc[2]); acc[3] = fmaf(w, f1.y, acc[3]);
                acc[4] = fmaf(w, f2.x, acc[4]); acc[5] = fmaf(w, f2.y, acc[5]);
                acc[6] = fmaf(w, f3.x, acc[6]); acc[7] = fmaf(w, f3.y, acc[7]);
            }
        }
    }

    // merge odd warp into even warp via smem
    if (sub == 1) {
#pragma unroll
        for (int r = 0; r < 8; r++) smA[nb][lane * 9 + r] = acc[r];
        if (lane == 0) { smS[nb][0] = s0; smS[nb][1] = s1; }
    }
    __syncthreads();
    if (sub == 0 && n < NN) {
#pragma unroll
        for (int r = 0; r < 8; r++) acc[r] += smA[nb][lane * 9 + r];
        s0 += smS[nb][0]; s1 += smS[nb][1];

        float i0 = 0.5f / (s0 + 1e-16f), i1 = 0.5f / (s1 + 1e-16f);
        float o[8];
#pragma unroll
        for (int r = 0; r < 8; r++) {
            float other = __shfl_xor_sync(FULL, acc[r], 16);
            o[r] = head ? fmaf(other, i0, acc[r] * i1) : fmaf(acc[r], i0, other * i1);
        }
        if (lane < 16) {
            float4 b0 = __ldg((const float4*)bias + 2 * lane);
            float4 b1 = __ldg((const float4*)bias + 2 * lane + 1);
            uint4 u;
            u.x = h2u(__float22half2_rn(make_float2(sig_(o[0] + b0.x), sig_(o[1] + b0.y))));
            u.y = h2u(__float22half2_rn(make_float2(sig_(o[2] + b0.z), sig_(o[3] + b0.w))));
            u.z = h2u(__float22half2_rn(make_float2(sig_(o[4] + b1.x), sig_(o[5] + b1.y))));
            u.w = h2u(__float22half2_rn(make_float2(sig_(o[6] + b1.z), sig_(o[7] + b1.w))));
            *(uint4*)(oh + (size_t)n * 128 + 8 * lane) = u;
        }
    }
}

// ---------------- pooling ----------------
__global__ void k_pool(const int* __restrict__ batch) {
    int j = threadIdx.x;
    int n0 = blockIdx.x * 128;
    int n1 = min(n0 + 128, NN);
    int m64 = d_i64;
    float a = 0.f;
    int curg = gi(batch, n0, m64);
    for (int n = n0; n < n1; n++) {
        int b = gi(batch, n, m64);
        if (b != curg) {
            atomicAdd(&d_pooled[curg * 128 + j], a);
            a = 0.f;
            curg = b;
        }
        float gate = d_eg[n] / (d_gs[b] + 1e-16f);
        a = fmaf(gate, __half2float(__ldg(&d_o2h[(size_t)n * 128 + j])), a);
    }
    atomicAdd(&d_pooled[curg * 128 + j], a);
}

__global__ void k_fin(const float* __restrict__ glw, const float* __restrict__ glb,
                      float* __restrict__ out) {
    int g = (blockIdx.x * blockDim.x + threadIdx.x) >> 5;
    int lane = threadIdx.x & 31;
    if (g >= GG) return;
    float4 p = ((const float4*)(d_pooled + g * 128))[lane];
    float4 w = __ldg((const float4*)glw + lane);
    float acc = warpSum(dot4(p, w));
    if (lane == 0) out[g] = sig_(acc + __ldg(glb));
}

// ---------------- launch ----------------
extern "C" void kernel_launch(void* const* d_in, const int* in_sizes, int n_in,
                              void* d_out, int out_size) {
    const int* x     = (const int*)d_in[0];
    const int* ei    = (const int*)d_in[1];
    const int* batch = (const int*)d_in[3];
    const float* emb0 = (const float*)d_in[4];
    const float* emb1 = (const float*)d_in[5];
    const float* emb2 = (const float*)d_in[6];
    const float* emb3 = (const float*)d_in[7];
    const float* emb4 = (const float*)d_in[8];
    const float* emb5 = (const float*)d_in[9];
    const float* W1  = (const float*)d_in[10];
    const float* as1 = (const float*)d_in[11];
    const float* ad1 = (const float*)d_in[12];
    const float* b1  = (const float*)d_in[13];
    const float* W2  = (const float*)d_in[14];
    const float* as2 = (const float*)d_in[15];
    const float* ad2 = (const float*)d_in[16];
    const float* b2  = (const float*)d_in[17];
    const float* gw1 = (const float*)d_in[18];
    const float* gb1 = (const float*)d_in[19];
    const float* bng = (const float*)d_in[20];
    const float* bnb = (const float*)d_in[21];
    const float* bnm = (const float*)d_in[22];
    const float* bnv = (const float*)d_in[23];
    const float* gw2 = (const float*)d_in[24];
    const float* gb2 = (const float*)d_in[25];
    const float* glw = (const float*)d_in[26];
    const float* glb = (const float*)d_in[27];
    float* out = (float*)d_out;

    __half* p_o1h; cudaGetSymbolAddress((void**)&p_o1h, d_o1h);
    __half* p_o2h; cudaGetSymbolAddress((void**)&p_o2h, d_o2h);
    unsigned* p_W2p;  cudaGetSymbolAddress((void**)&p_W2p, d_W2p);
    unsigned* p_gw1p; cudaGetSymbolAddress((void**)&p_gw1p, d_gw1p);

    const int gNODE = NN / 8;
    const int gGAT = (NN + 3) / 4;       // 2 warps per node, 4 nodes per 256-thr block
    const int gEDGE = (ET + 255) / 256;
    const int gHM = (NN + 63) / 64;

    k_prep<<<(NN + 255) / 256, 256>>>(ei);                               // 1
    k_T1<<<50, 256>>>(emb0, emb1, emb2, emb3, emb4, emb5, W1);           // 2
    k_embed<<<gNODE, 256>>>(x, as1, ad1);                                // 3
    k_hist<<<(EE + 255) / 256, 256>>>(ei);                               // 4 <- profiled
    k_pack<<<50, 256>>>(W2, gw1, gb1, bng, bnb, bnm, bnv);               // 5
    k_scan1<<<NB, 1024>>>();                                             // 6
    k_scan23<<<NB, 1024>>>();                                            // 7
    k_scatter<<<gEDGE, 256>>>(ei);                                       // 8

    k_gat<<<gGAT, 256>>>(b1, p_o1h);                                     // 9
    k_hmma2<<<gHM, 256>>>(p_o1h, p_W2p, as2, ad2, NN);                   // 10
    k_gat<<<gGAT, 256>>>(b2, p_o2h);                                     // 11

    k_hmmaG<<<gHM, 256>>>(p_o2h, p_gw1p, gw2, gb2, batch, NN);           // 12
    k_pool<<<(NN + 127) / 128, 128>>>(batch);                            // 13
    k_fin<<<(GG * 32 + 255) / 256, 256>>>(glw, glb, out);                // 14

    (void)in_sizes; (void)n_in; (void)out_size;
}

// round 14
// speedup vs baseline: 1.0924x; 1.0924x over previous
#include <cuda_runtime.h>
#include <cuda_fp16.h>
#include <math.h>

#define NN 100000
#define EE 800000
#define ET (EE + NN)
#define GG 128
#define NB 98   /* ceil(NN/1024) */
#define FULL 0xffffffffu
#define LOG2E 1.4426950408889634f

typedef unsigned long long ull;

// ---------------- scratch (static device memory) ----------------
__device__ __half d_hh[(size_t)NN * 256];    // h fp16 (51 MB, L2-resident)
__device__ __half d_o1h[(size_t)NN * 128];   // out1 fp16
__device__ __half d_o2h[(size_t)NN * 128];   // out2 fp16
__device__ float d_als[NN * 2], d_ald[NN * 2];   // pre-scaled by log2(e)
__device__ float d_eg[NN];
__device__ float d_gs[GG];
__device__ float d_pooled[GG * 128];
__device__ float d_T1[50 * 256];
__device__ unsigned d_W2p[8 * 32 * 32 * 2];  // prepacked B frags
__device__ unsigned d_gw1p[8 * 16 * 32 * 2];
__device__ float d_gA[128], d_gB[128];       // folded BN for gate
__device__ int d_deg[NN], d_incl[NN], d_ptr[NN + 1], d_pos[NN];
__device__ int d_srcs[ET];
__device__ int d_bsum[128];
__device__ int d_i64;
__device__ int d_ctr;                        // pool completion counter (self-resetting)

__constant__ int c_voff[6] = {0, 33, 38, 41, 45, 47};

// ---------------- helpers ----------------
__device__ __forceinline__ float sig_(float x) { return 1.f / (1.f + __expf(-x)); }
__device__ __forceinline__ float ex2_(float x) {
    float r;
    asm("ex2.approx.ftz.f32 %0, %1;" : "=f"(r) : "f"(x));
    return r;
}
__device__ __forceinline__ float warpSum(float v) {
#pragma unroll
    for (int o = 16; o; o >>= 1) v += __shfl_xor_sync(FULL, v, o);
    return v;
}
__device__ __forceinline__ int warpSumI(int v) {
#pragma unroll
    for (int o = 16; o; o >>= 1) v += __shfl_xor_sync(FULL, v, o);
    return v;
}
__device__ __forceinline__ float dot4(float4 a, float4 b) {
    return a.x * b.x + a.y * b.y + a.z * b.z + a.w * b.w;
}
__device__ __forceinline__ int gi(const int* __restrict__ p, int i, int m64) {
    return p[m64 ? (i << 1) : i];
}
__device__ __forceinline__ unsigned h2u(__half2 h) { return *(unsigned*)&h; }

// ---------------- init0: detect + deg=1 + zero pooled/gs + pack W2/gw1/BN + T1 ----------------
// grid = 512 blocks x 256 thr. Blocks 0..49 additionally compute T1 (row = blockIdx).
__global__ void k_init0(const int* __restrict__ ei,
                        const float* __restrict__ e0, const float* __restrict__ e1,
                        const float* __restrict__ e2, const float* __restrict__ e3,
                        const float* __restrict__ e4, const float* __restrict__ e5,
                        const float* __restrict__ W1, const float* __restrict__ W2,
                        const float* __restrict__ gw1, const float* __restrict__ gb1,
                        const float* __restrict__ bng, const float* __restrict__ bnb,
                        const float* __restrict__ bnm, const float* __restrict__ bnv) {
    int i = blockIdx.x * 256 + threadIdx.x;
    if (i == 0)
        d_i64 = ((ei[1] | ei[3] | ei[5] | ei[7] | ei[9]) == 0) ? 1 : 0;
    if (i < NN) d_deg[i] = 1;
    if (i < GG * 128) d_pooled[i] = 0.f;
    if (i < GG) d_gs[i] = 0.f;
    // pack
    if (i < 8192) {
        int lane = i & 31, nt = (i >> 5) & 31, kk = i >> 10;
        int k0 = kk * 16 + (lane & 3) * 2, n = nt * 8 + (lane >> 2);
        unsigned lo = h2u(__float22half2_rn(make_float2(W2[k0 * 256 + n],       W2[(k0 + 1) * 256 + n])));
        unsigned hi = h2u(__float22half2_rn(make_float2(W2[(k0 + 8) * 256 + n], W2[(k0 + 9) * 256 + n])));
        d_W2p[i * 2] = lo; d_W2p[i * 2 + 1] = hi;
    } else if (i < 8192 + 4096) {
        int u = i - 8192;
        int lane = u & 31, nt = (u >> 5) & 15, kk = u >> 9;
        int k0 = kk * 16 + (lane & 3) * 2, n = nt * 8 + (lane >> 2);
        unsigned lo = h2u(__float22half2_rn(make_float2(gw1[k0 * 128 + n],       gw1[(k0 + 1) * 128 + n])));
        unsigned hi = h2u(__float22half2_rn(make_float2(gw1[(k0 + 8) * 128 + n], gw1[(k0 + 9) * 128 + n])));
        d_gw1p[u * 2] = lo; d_gw1p[u * 2 + 1] = hi;
    } else if (i < 8192 + 4096 + 128) {
        int j = i - 8192 - 4096;
        float a = rsqrtf(bnv[j] + 1e-5f) * bng[j];
        d_gA[j] = a;
        d_gB[j] = (gb1[j] - bnm[j]) * a + bnb[j];
    }
    // T1 (blocks 0..49)
    int row = blockIdx.x;
    if (row < 50) {
        int j = threadIdx.x;
        int t, v;
        if (row < 33)      { t = 0; v = row; }
        else if (row < 38) { t = 1; v = row - 33; }
        else if (row < 41) { t = 2; v = row - 38; }
        else if (row < 45) { t = 3; v = row - 41; }
        else if (row < 47) { t = 4; v = row - 45; }
        else               { t = 5; v = row - 47; }
        const float* emb = (t == 0) ? e0 : (t == 1) ? e1 : (t == 2) ? e2 : (t == 3) ? e3 : (t == 4) ? e4 : e5;
        float acc = 0.f;
#pragma unroll 8
        for (int c = 0; c < 64; c++) acc = fmaf(emb[v * 64 + c], W1[(size_t)(t * 64 + c) * 256 + j], acc);
        d_T1[row * 256 + j] = acc;
    }
}

// ---------------- h1 embed + fused attention logits ----------------
__global__ void k_embed(const int* __restrict__ x,
                        const float* __restrict__ as_, const float* __restrict__ ad_) {
    int n = blockIdx.x * 8 + (threadIdx.x >> 5);
    int lane = threadIdx.x & 31;
    if (n >= NN) return;
    int m64 = d_i64;
    int xv = 0;
    if (lane < 6) xv = gi(x, n * 6 + lane, m64);
    int rows[6];
#pragma unroll
    for (int i = 0; i < 6; i++) rows[i] = c_voff[i] + __shfl_sync(FULL, xv, i);
    float4 a0 = make_float4(0.f, 0.f, 0.f, 0.f), a1 = make_float4(0.f, 0.f, 0.f, 0.f);
#pragma unroll
    for (int i = 0; i < 6; i++) {
        const float4* T = (const float4*)(d_T1 + rows[i] * 256);
        float4 t0 = T[lane], t1 = T[lane + 32];
        a0.x += t0.x; a0.y += t0.y; a0.z += t0.z; a0.w += t0.w;
        a1.x += t1.x; a1.y += t1.y; a1.z += t1.z; a1.w += t1.w;
    }
    uint2 u0, u1;
    u0.x = h2u(__float22half2_rn(make_float2(a0.x, a0.y)));
    u0.y = h2u(__float22half2_rn(make_float2(a0.z, a0.w)));
    u1.x = h2u(__float22half2_rn(make_float2(a1.x, a1.y)));
    u1.y = h2u(__float22half2_rn(make_float2(a1.z, a1.w)));
    *(uint2*)(d_hh + (size_t)n * 256 + 4 * lane) = u0;
    *(uint2*)(d_hh + (size_t)n * 256 + 128 + 4 * lane) = u1;
    float4 s0 = __ldg((const float4*)as_ + lane), s1 = __ldg((const float4*)as_ + lane + 32);
    float4 t0 = __ldg((const float4*)ad_ + lane), t1 = __ldg((const float4*)ad_ + lane + 32);
    float ps0 = warpSum(dot4(a0, s0));
    float ps1 = warpSum(dot4(a1, s1));
    float pd0 = warpSum(dot4(a0, t0));
    float pd1 = warpSum(dot4(a1, t1));
    if (lane == 0) {
        d_als[n * 2] = ps0 * LOG2E; d_als[n * 2 + 1] = ps1 * LOG2E;
        d_ald[n * 2] = pd0 * LOG2E; d_ald[n * 2 + 1] = pd1 * LOG2E;
    }
}

// ---------------- CSR build ----------------
__global__ void k_hist(const int* __restrict__ ei) {
    int t = blockIdx.x * blockDim.x + threadIdx.x;
    if (t < EE) atomicAdd(&d_deg[gi(ei, EE + t, d_i64)], 1);
}
__global__ void k_scan1() {
    __shared__ int ws[32];
    int i = blockIdx.x * 1024 + threadIdx.x;
    int lane = threadIdx.x & 31, w = threadIdx.x >> 5;
    int x = (i < NN) ? d_deg[i] : 0;
#pragma unroll
    for (int o = 1; o < 32; o <<= 1) { int y = __shfl_up_sync(FULL, x, o); if (lane >= o) x += y; }
    if (lane == 31) ws[w] = x;
    __syncthreads();
    if (w == 0) {
        int t = ws[lane];
#pragma unroll
        for (int o = 1; o < 32; o <<= 1) { int y = __shfl_up_sync(FULL, t, o); if (lane >= o) t += y; }
        ws[lane] = t;
    }
    __syncthreads();
    x += (w > 0) ? ws[w - 1] : 0;
    if (i < NN) d_incl[i] = x;
    if (threadIdx.x == 1023) d_bsum[blockIdx.x] = x;
}
__global__ void k_scan23() {
    __shared__ int off_s;
    int tid = threadIdx.x;
    if (tid < 32) {
        int v = 0;
        for (int b = tid; b < blockIdx.x; b += 32) v += d_bsum[b];
        v = warpSumI(v);
        if (tid == 0) off_s = v;
    }
    __syncthreads();
    int i = blockIdx.x * 1024 + tid;
    if (i < NN) {
        int e = d_incl[i] - d_deg[i] + off_s;
        d_ptr[i] = e;
        d_pos[i] = e;
    }
    if (i == 0) d_ptr[NN] = ET;
}
__global__ void k_scatter(const int* __restrict__ ei) {
    int t = blockIdx.x * blockDim.x + threadIdx.x;
    if (t >= ET) return;
    int m64 = d_i64;
    int s, d;
    if (t < EE) { s = gi(ei, t, m64); d = gi(ei, EE + t, m64); }
    else { s = d = t - EE; }
    d_srcs[atomicAdd(&d_pos[d], 1)] = s;
}

// ---------------- HMMA layer-2 GEMM + fused als/ald ----------------
__global__ void k_hmma2(const __half* __restrict__ A, const unsigned* __restrict__ Bp,
                        const float* __restrict__ as_, const float* __restrict__ ad_, int M) {
    constexpr int NT = 32, NTW = 16;
    __shared__ __half As[64 * 136];
    int tid = threadIdx.x;
    int wid = tid >> 5, lane = tid & 31;
    int wm = wid >> 1, wn = wid & 1;
    int row0 = blockIdx.x * 64;

    {
        const uint4* Ag = (const uint4*)(A + (size_t)row0 * 128);
        uint4* Asm = (uint4*)As;
#pragma unroll
        for (int u = 0; u < 4; u++) {
            int f = tid + 256 * u;
            int r = f >> 4, c4 = f & 15;
            uint4 v = make_uint4(0, 0, 0, 0);
            if (row0 + r < M) v = __ldg(Ag + f);
            Asm[r * 17 + c4] = v;
        }
    }
    __syncthreads();

    float acc[NTW][4];
#pragma unroll
    for (int t = 0; t < NTW; t++) acc[t][0] = acc[t][1] = acc[t][2] = acc[t][3] = 0.f;
    int mrow = wm * 16;
    int arow = lane >> 2, acol = (lane & 3) * 2;
    const __half* Ab0 = As + (mrow + arow) * 136;
    const __half* Ab1 = As + (mrow + arow + 8) * 136;

#pragma unroll
    for (int kk = 0; kk < 8; kk++) {
        unsigned a0 = *(const unsigned*)(Ab0 + kk * 16 + acol);
        unsigned a1 = *(const unsigned*)(Ab1 + kk * 16 + acol);
        unsigned a2 = *(const unsigned*)(Ab0 + kk * 16 + acol + 8);
        unsigned a3 = *(const unsigned*)(Ab1 + kk * 16 + acol + 8);
#pragma unroll
        for (int t = 0; t < NTW; t++) {
            int nt = wn * NTW + t;
            uint2 b = __ldg((const uint2*)Bp + (kk * NT + nt) * 32 + lane);
            asm volatile(
                "mma.sync.aligned.m16n8k16.row.col.f32.f16.f16.f32 "
                "{%0,%1,%2,%3}, {%4,%5,%6,%7}, {%8,%9}, {%0,%1,%2,%3};"
                : "+f"(acc[t][0]), "+f"(acc[t][1]), "+f"(acc[t][2]), "+f"(acc[t][3])
                : "r"(a0), "r"(a1), "r"(a2), "r"(a3), "r"(b.x), "r"(b.y));
        }
    }

    int grow = row0 + mrow + arow;
    int coff = wn * 128 + (lane & 3) * 2;
    const float* S = as_ + wn * 128;
    const float* D = ad_ + wn * 128;
    float s0p = 0.f, d0p = 0.f, s1p = 0.f, d1p = 0.f;
#pragma unroll
    for (int t = 0; t < NTW; t++) {
        int lc = (lane & 3) * 2 + t * 8;
        float sa = __ldg(&S[lc]), sb = __ldg(&S[lc + 1]);
        float da = __ldg(&D[lc]), db = __ldg(&D[lc + 1]);
        s0p += acc[t][0] * sa + acc[t][1] * sb;
        d0p += acc[t][0] * da + acc[t][1] * db;
        s1p += acc[t][2] * sa + acc[t][3] * sb;
        d1p += acc[t][2] * da + acc[t][3] * db;
        int col = coff + t * 8;
        if (grow < M)
            *(__half2*)(d_hh + (size_t)grow * 256 + col) =
                __float22half2_rn(make_float2(acc[t][0], acc[t][1]));
        if (grow + 8 < M)
            *(__half2*)(d_hh + (size_t)(grow + 8) * 256 + col) =
                __float22half2_rn(make_float2(acc[t][2], acc[t][3]));
    }
#pragma unroll
    for (int o = 1; o < 4; o <<= 1) {
        s0p += __shfl_xor_sync(FULL, s0p, o);
        d0p += __shfl_xor_sync(FULL, d0p, o);
        s1p += __shfl_xor_sync(FULL, s1p, o);
        d1p += __shfl_xor_sync(FULL, d1p, o);
    }
    if ((lane & 3) == 0) {
        if (grow < M)     { d_als[grow * 2 + wn] = s0p * LOG2E;       d_ald[grow * 2 + wn] = d0p * LOG2E; }
        if (grow + 8 < M) { d_als[(grow + 8) * 2 + wn] = s1p * LOG2E; d_ald[(grow + 8) * 2 + wn] = d1p * LOG2E; }
    }
}

// ---------------- HMMA gate GEMM: fused BN+relu+dot(gw2)+exp+graph-sum ----------------
__global__ void k_hmmaG(const __half* __restrict__ A, const unsigned* __restrict__ Bp,
                        const float* __restrict__ gw2, const float* __restrict__ gb2,
                        const int* __restrict__ batch, int M) {
    constexpr int NT = 16, NTW = 8;
    __shared__ __half As[64 * 136];
    __shared__ float slog[64];
    int tid = threadIdx.x;
    int wid = tid >> 5, lane = tid & 31;
    int wm = wid >> 1, wn = wid & 1;
    int row0 = blockIdx.x * 64;

    if (tid < 64) slog[tid] = 0.f;
    {
        const uint4* Ag = (const uint4*)(A + (size_t)row0 * 128);
        uint4* Asm = (uint4*)As;
#pragma unroll
        for (int u = 0; u < 4; u++) {
            int f = tid + 256 * u;
            int r = f >> 4, c4 = f & 15;
            uint4 v = make_uint4(0, 0, 0, 0);
            if (row0 + r < M) v = __ldg(Ag + f);
            Asm[r * 17 + c4] = v;
        }
    }
    __syncthreads();

    float acc[NTW][4];
#pragma unroll
    for (int t = 0; t < NTW; t++) acc[t][0] = acc[t][1] = acc[t][2] = acc[t][3] = 0.f;
    int mrow = wm * 16;
    int arow = lane >> 2, acol = (lane & 3) * 2;
    const __half* Ab0 = As + (mrow + arow) * 136;
    const __half* Ab1 = As + (mrow + arow + 8) * 136;

#pragma unroll
    for (int kk = 0; kk < 8; kk++) {
        unsigned a0 = *(const unsigned*)(Ab0 + kk * 16 + acol);
        unsigned a1 = *(const unsigned*)(Ab1 + kk * 16 + acol);
        unsigned a2 = *(const unsigned*)(Ab0 + kk * 16 + acol + 8);
        unsigned a3 = *(const unsigned*)(Ab1 + kk * 16 + acol + 8);
#pragma unroll
        for (int t = 0; t < NTW; t++) {
            int nt = wn * NTW + t;
            uint2 b = __ldg((const uint2*)Bp + (kk * NT + nt) * 32 + lane);
            asm volatile(
                "mma.sync.aligned.m16n8k16.row.col.f32.f16.f16.f32 "
                "{%0,%1,%2,%3}, {%4,%5,%6,%7}, {%8,%9}, {%0,%1,%2,%3};"
                : "+f"(acc[t][0]), "+f"(acc[t][1]), "+f"(acc[t][2]), "+f"(acc[t][3])
                : "r"(a0), "r"(a1), "r"(a2), "r"(a3), "r"(b.x), "r"(b.y));
        }
    }

    float p0 = 0.f, p1 = 0.f;
#pragma unroll
    for (int t = 0; t < NTW; t++) {
        int c = wn * 64 + (lane & 3) * 2 + t * 8;
        float A0 = d_gA[c], A1 = d_gA[c + 1];
        float B0 = d_gB[c], B1 = d_gB[c + 1];
        float w0 = __ldg(&gw2[c]), w1 = __ldg(&gw2[c + 1]);
        float v;
        v = fmaf(acc[t][0], A0, B0); v = v > 0.f ? v : 0.f; p0 = fmaf(v, w0, p0);
        v = fmaf(acc[t][1], A1, B1); v = v > 0.f ? v : 0.f; p0 = fmaf(v, w1, p0);
        v = fmaf(acc[t][2], A0, B0); v = v > 0.f ? v : 0.f; p1 = fmaf(v, w0, p1);
        v = fmaf(acc[t][3], A1, B1); v = v > 0.f ? v : 0.f; p1 = fmaf(v, w1, p1);
    }
#pragma unroll
    for (int o = 1; o < 4; o <<= 1) {
        p0 += __shfl_xor_sync(FULL, p0, o);
        p1 += __shfl_xor_sync(FULL, p1, o);
    }
    int r0 = mrow + arow;
    if ((lane & 3) == 0) {
        atomicAdd(&slog[r0], p0);
        atomicAdd(&slog[r0 + 8], p1);
    }
    __syncthreads();
    if (tid < 64) {
        int n = row0 + tid;
        if (n < M) {
            float e = __expf(slog[tid] + __ldg(gb2));
            d_eg[n] = e;
            atomicAdd(&d_gs[gi(batch, n, d_i64)], e);
        }
    }
}

// ---------------- fused GAT: R11 pipelined half gather, warp per dst ----------------
__global__ void k_gat(const float* __restrict__ bias, __half* __restrict__ oh) {
    int n = blockIdx.x * 8 + (threadIdx.x >> 5);
    int lane = threadIdx.x & 31;
    if (n >= NN) return;
    int p0 = d_ptr[n], p1 = d_ptr[n + 1];
    float2 adv = ((const float2*)d_ald)[n];
    int head = lane >> 4;
    const float2* ALS = (const float2*)d_als;

    float acc[8];
#pragma unroll
    for (int r = 0; r < 8; r++) acc[r] = 0.f;
    float s0 = 0.f, s1 = 0.f;

    // 1-ahead software pipeline (deg >= 1 guaranteed by self-loop)
    int sx = __ldg(&d_srcs[p0]);
    float2 a_n = __ldg(ALS + sx);
    uint4 q_n = __ldg((const uint4*)(d_hh + (size_t)sx * 256) + lane);

#pragma unroll 2
    for (int j = p0; j < p1; j++) {
        float2 a_c = a_n;
        uint4 q_c = q_n;
        int jn = j + 1;
        if (jn < p1) {
            int sv = __ldg(&d_srcs[jn]);
            a_n = __ldg(ALS + sv);
            q_n = __ldg((const uint4*)(d_hh + (size_t)sv * 256) + lane);
        }
        float e0 = a_c.x + adv.x; e0 = e0 > 0.f ? e0 : 0.2f * e0;
        float e1 = a_c.y + adv.y; e1 = e1 > 0.f ? e1 : 0.2f * e1;
        float w0 = ex2_(e0), w1 = ex2_(e1);
        s0 += w0; s1 += w1;
        float w = head ? w1 : w0;
        __half2* hp = (__half2*)&q_c;
        float2 f0 = __half22float2(hp[0]), f1 = __half22float2(hp[1]);
        float2 f2 = __half22float2(hp[2]), f3 = __half22float2(hp[3]);
        acc[0] = fmaf(w, f0.x, acc[0]); acc[1] = fmaf(w, f0.y, acc[1]);
        acc[2] = fmaf(w, f1.x, acc[2]); acc[3] = fmaf(w, f1.y, acc[3]);
        acc[4] = fmaf(w, f2.x, acc[4]); acc[5] = fmaf(w, f2.y, acc[5]);
        acc[6] = fmaf(w, f3.x, acc[6]); acc[7] = fmaf(w, f3.y, acc[7]);
    }
    float i0 = 0.5f / (s0 + 1e-16f), i1 = 0.5f / (s1 + 1e-16f);
    float o[8];
#pragma unroll
    for (int r = 0; r < 8; r++) {
        float other = __shfl_xor_sync(FULL, acc[r], 16);
        o[r] = head ? fmaf(other, i0, acc[r] * i1) : fmaf(acc[r], i0, other * i1);
    }
    if (lane < 16) {
        float4 b0 = __ldg((const float4*)bias + 2 * lane);
        float4 b1 = __ldg((const float4*)bias + 2 * lane + 1);
        uint4 u;
        u.x = h2u(__float22half2_rn(make_float2(sig_(o[0] + b0.x), sig_(o[1] + b0.y))));
        u.y = h2u(__float22half2_rn(make_float2(sig_(o[2] + b0.z), sig_(o[3] + b0.w))));
        u.z = h2u(__float22half2_rn(make_float2(sig_(o[4] + b1.x), sig_(o[5] + b1.y))));
        u.w = h2u(__float22half2_rn(make_float2(sig_(o[6] + b1.z), sig_(o[7] + b1.w))));
        *(uint4*)(oh + (size_t)n * 128 + 8 * lane) = u;
    }
}

// ---------------- pooling (last block also computes final output) ----------------
__global__ void k_pool(const int* __restrict__ batch,
                       const float* __restrict__ glw, const float* __restrict__ glb,
                       float* __restrict__ out) {
    int j = threadIdx.x;
    int n0 = blockIdx.x * 128;
    int n1 = min(n0 + 128, NN);
    int m64 = d_i64;
    float a = 0.f;
    int curg = gi(batch, n0, m64);
    for (int n = n0; n < n1; n++) {
        int b = gi(batch, n, m64);
        if (b != curg) {
            atomicAdd(&d_pooled[curg * 128 + j], a);
            a = 0.f;
            curg = b;
        }
        float gate = d_eg[n] / (d_gs[b] + 1e-16f);
        a = fmaf(gate, __half2float(__ldg(&d_o2h[(size_t)n * 128 + j])), a);
    }
    atomicAdd(&d_pooled[curg * 128 + j], a);

    // last-block finalization
    __shared__ int isLast;
    __threadfence();
    __syncthreads();
    if (j == 0) {
        int old = atomicAdd(&d_ctr, 1);
        isLast = (old == gridDim.x - 1);
        if (isLast) d_ctr = 0;   // reset for next graph replay
    }
    __syncthreads();
    if (isLast) {
        __threadfence();
        // 128 threads = 4 warps; warp w handles graphs [w*32, w*32+32), lane-parallel dot
        int w = j >> 5, lane = j & 31;
        for (int g = w * 32; g < w * 32 + 32; g++) {
            float p = d_pooled[g * 128 + lane] * __ldg(&glw[lane])
                    + d_pooled[g * 128 + lane + 32] * __ldg(&glw[lane + 32])
                    + d_pooled[g * 128 + lane + 64] * __ldg(&glw[lane + 64])
                    + d_pooled[g * 128 + lane + 96] * __ldg(&glw[lane + 96]);
            p = warpSum(p);
            if (lane == 0) out[g] = sig_(p + __ldg(glb));
        }
    }
}

// ---------------- launch ----------------
extern "C" void kernel_launch(void* const* d_in, const int* in_sizes, int n_in,
                              void* d_out, int out_size) {
    const int* x     = (const int*)d_in[0];
    const int* ei    = (const int*)d_in[1];
    const int* batch = (const int*)d_in[3];
    const float* emb0 = (const float*)d_in[4];
    const float* emb1 = (const float*)d_in[5];
    const float* emb2 = (const float*)d_in[6];
    const float* emb3 = (const float*)d_in[7];
    const float* emb4 = (const float*)d_in[8];
    const float* emb5 = (const float*)d_in[9];
    const float* W1  = (const float*)d_in[10];
    const float* as1 = (const float*)d_in[11];
    const float* ad1 = (const float*)d_in[12];
    const float* b1  = (const float*)d_in[13];
    const float* W2  = (const float*)d_in[14];
    const float* as2 = (const float*)d_in[15];
    const float* ad2 = (const float*)d_in[16];
    const float* b2  = (const float*)d_in[17];
    const float* gw1 = (const float*)d_in[18];
    const float* gb1 = (const float*)d_in[19];
    const float* bng = (const float*)d_in[20];
    const float* bnb = (const float*)d_in[21];
    const float* bnm = (const float*)d_in[22];
    const float* bnv = (const float*)d_in[23];
    const float* gw2 = (const float*)d_in[24];
    const float* gb2 = (const float*)d_in[25];
    const float* glw = (const float*)d_in[26];
    const float* glb = (const float*)d_in[27];
    float* out = (float*)d_out;

    __half* p_o1h; cudaGetSymbolAddress((void**)&p_o1h, d_o1h);
    __half* p_o2h; cudaGetSymbolAddress((void**)&p_o2h, d_o2h);
    unsigned* p_W2p;  cudaGetSymbolAddress((void**)&p_W2p, d_W2p);
    unsigned* p_gw1p; cudaGetSymbolAddress((void**)&p_gw1p, d_gw1p);

    const int gNODE = NN / 8;
    const int gEDGE = (ET + 255) / 256;
    const int gHM = (NN + 63) / 64;

    k_init0<<<512, 256>>>(ei, emb0, emb1, emb2, emb3, emb4, emb5, W1, W2,
                          gw1, gb1, bng, bnb, bnm, bnv);                 // 1
    k_hist<<<(EE + 255) / 256, 256>>>(ei);                               // 2
    k_scan1<<<NB, 1024>>>();                                             // 3
    k_embed<<<gNODE, 256>>>(x, as1, ad1);                                // 4 <- profiled
    k_scan23<<<NB, 1024>>>();                                            // 5
    k_scatter<<<gEDGE, 256>>>(ei);                                       // 6

    k_gat<<<gNODE, 256>>>(b1, p_o1h);                                    // 7
    k_hmma2<<<gHM, 256>>>(p_o1h, p_W2p, as2, ad2, NN);                   // 8
    k_gat<<<gNODE, 256>>>(b2, p_o2h);                                    // 9

    k_hmmaG<<<gHM, 256>>>(p_o2h, p_gw1p, gw2, gb2, batch, NN);           // 10
    k_pool<<<(NN + 127) / 128, 128>>>(batch, glw, glb, out);             // 11

    (void)in_sizes; (void)n_in; (void)out_size;
}

// round 15
// speedup vs baseline: 1.1006x; 1.0075x over previous
#include <cuda_runtime.h>
#include <cuda_fp16.h>
#include <math.h>

#define NN 100000
#define EE 800000
#define ET (EE + NN)
#define GG 128
#define NB 98   /* ceil(NN/1024) */
#define FULL 0xffffffffu
#define LOG2E 1.4426950408889634f

typedef unsigned long long ull;

// ---------------- scratch (static device memory) ----------------
__device__ __half d_hh[(size_t)NN * 256];    // h fp16 (51 MB, L2-resident)
__device__ __half d_o1h[(size_t)NN * 128];   // out1 fp16
__device__ __half d_o2h[(size_t)NN * 128];   // out2 fp16
__device__ float d_als[NN * 2], d_ald[NN * 2];   // pre-scaled by log2(e)
__device__ float d_eg[NN];
__device__ float d_gs[GG];
__device__ float d_pooled[GG * 128];
__device__ float d_T1[50 * 256];
__device__ __half d_T1h[50 * 256];           // fp16 copy for k_embed gather
__device__ float d_S[50 * 4];                // per-row (s0,s1,d0,d1) * LOG2E
__device__ unsigned d_W2p[8 * 32 * 32 * 2];  // prepacked B frags
__device__ unsigned d_gw1p[8 * 16 * 32 * 2];
__device__ float d_gA[128], d_gB[128];       // folded BN for gate
__device__ int d_deg[NN], d_incl[NN], d_ptr[NN + 1], d_pos[NN];
__device__ int d_srcs[ET];
__device__ int d_bsum[128];
__device__ int d_i64;
__device__ int d_ctr;                        // pool completion counter (self-resetting)

__constant__ int c_voff[6] = {0, 33, 38, 41, 45, 47};

// ---------------- helpers ----------------
__device__ __forceinline__ float sig_(float x) { return 1.f / (1.f + __expf(-x)); }
__device__ __forceinline__ float ex2_(float x) {
    float r;
    asm("ex2.approx.ftz.f32 %0, %1;" : "=f"(r) : "f"(x));
    return r;
}
__device__ __forceinline__ float warpSum(float v) {
#pragma unroll
    for (int o = 16; o; o >>= 1) v += __shfl_xor_sync(FULL, v, o);
    return v;
}
__device__ __forceinline__ int warpSumI(int v) {
#pragma unroll
    for (int o = 16; o; o >>= 1) v += __shfl_xor_sync(FULL, v, o);
    return v;
}
__device__ __forceinline__ float dot4(float4 a, float4 b) {
    return a.x * b.x + a.y * b.y + a.z * b.z + a.w * b.w;
}
__device__ __forceinline__ int gi(const int* __restrict__ p, int i, int m64) {
    return p[m64 ? (i << 1) : i];
}
__device__ __forceinline__ unsigned h2u(__half2 h) { return *(unsigned*)&h; }

// ---------------- init0: detect + deg=1 + zeros + pack + T1 (fp32 & fp16) ----------------
__global__ void k_init0(const int* __restrict__ ei,
                        const float* __restrict__ e0, const float* __restrict__ e1,
                        const float* __restrict__ e2, const float* __restrict__ e3,
                        const float* __restrict__ e4, const float* __restrict__ e5,
                        const float* __restrict__ W1, const float* __restrict__ W2,
                        const float* __restrict__ gw1, const float* __restrict__ gb1,
                        const float* __restrict__ bng, const float* __restrict__ bnb,
                        const float* __restrict__ bnm, const float* __restrict__ bnv) {
    int i = blockIdx.x * 256 + threadIdx.x;
    if (i == 0)
        d_i64 = ((ei[1] | ei[3] | ei[5] | ei[7] | ei[9]) == 0) ? 1 : 0;
    if (i < NN) d_deg[i] = 1;
    if (i < GG * 128) d_pooled[i] = 0.f;
    if (i < GG) d_gs[i] = 0.f;
    if (i < 8192) {
        int lane = i & 31, nt = (i >> 5) & 31, kk = i >> 10;
        int k0 = kk * 16 + (lane & 3) * 2, n = nt * 8 + (lane >> 2);
        unsigned lo = h2u(__float22half2_rn(make_float2(W2[k0 * 256 + n],       W2[(k0 + 1) * 256 + n])));
        unsigned hi = h2u(__float22half2_rn(make_float2(W2[(k0 + 8) * 256 + n], W2[(k0 + 9) * 256 + n])));
        d_W2p[i * 2] = lo; d_W2p[i * 2 + 1] = hi;
    } else if (i < 8192 + 4096) {
        int u = i - 8192;
        int lane = u & 31, nt = (u >> 5) & 15, kk = u >> 9;
        int k0 = kk * 16 + (lane & 3) * 2, n = nt * 8 + (lane >> 2);
        unsigned lo = h2u(__float22half2_rn(make_float2(gw1[k0 * 128 + n],       gw1[(k0 + 1) * 128 + n])));
        unsigned hi = h2u(__float22half2_rn(make_float2(gw1[(k0 + 8) * 128 + n], gw1[(k0 + 9) * 128 + n])));
        d_gw1p[u * 2] = lo; d_gw1p[u * 2 + 1] = hi;
    } else if (i < 8192 + 4096 + 128) {
        int j = i - 8192 - 4096;
        float a = rsqrtf(bnv[j] + 1e-5f) * bng[j];
        d_gA[j] = a;
        d_gB[j] = (gb1[j] - bnm[j]) * a + bnb[j];
    }
    // T1 (blocks 0..49)
    int row = blockIdx.x;
    if (row < 50) {
        int j = threadIdx.x;
        int t, v;
        if (row < 33)      { t = 0; v = row; }
        else if (row < 38) { t = 1; v = row - 33; }
        else if (row < 41) { t = 2; v = row - 38; }
        else if (row < 45) { t = 3; v = row - 41; }
        else if (row < 47) { t = 4; v = row - 45; }
        else               { t = 5; v = row - 47; }
        const float* emb = (t == 0) ? e0 : (t == 1) ? e1 : (t == 2) ? e2 : (t == 3) ? e3 : (t == 4) ? e4 : e5;
        float acc = 0.f;
#pragma unroll 8
        for (int c = 0; c < 64; c++) acc = fmaf(emb[v * 64 + c], W1[(size_t)(t * 64 + c) * 256 + j], acc);
        d_T1[row * 256 + j] = acc;
        d_T1h[row * 256 + j] = __float2half_rn(acc);
    }
}

// ---------------- S table: S[row] = (T1row·as1_h, ..., T1row·ad1_h) * LOG2E ----------------
__global__ void k_S(const float* __restrict__ as_, const float* __restrict__ ad_) {
    int t = threadIdx.x;
    if (t >= 200) return;
    int row = t >> 2, q = t & 3, h = q & 1;
    const float* a = (q < 2) ? as_ : ad_;
    float acc = 0.f;
#pragma unroll 8
    for (int c = 0; c < 128; c++)
        acc = fmaf(d_T1[row * 256 + h * 128 + c], a[h * 128 + c], acc);
    d_S[row * 4 + q] = acc * LOG2E;
}

// ---------------- h1 embed (fp16 T1 gather) + table-based attention logits ----------------
__global__ void k_embed(const int* __restrict__ x) {
    int n = blockIdx.x * 8 + (threadIdx.x >> 5);
    int lane = threadIdx.x & 31;
    if (n >= NN) return;
    int m64 = d_i64;
    int xv = 0;
    if (lane < 6) xv = gi(x, n * 6 + lane, m64);
    int rows[6];
#pragma unroll
    for (int i = 0; i < 6; i++) rows[i] = c_voff[i] + __shfl_sync(FULL, xv, i);

    float acc[8];
#pragma unroll
    for (int r = 0; r < 8; r++) acc[r] = 0.f;
#pragma unroll
    for (int i = 0; i < 6; i++) {
        uint4 q = *(const uint4*)(d_T1h + rows[i] * 256 + lane * 8);
        __half2* hp = (__half2*)&q;
        float2 f0 = __half22float2(hp[0]), f1 = __half22float2(hp[1]);
        float2 f2 = __half22float2(hp[2]), f3 = __half22float2(hp[3]);
        acc[0] += f0.x; acc[1] += f0.y; acc[2] += f1.x; acc[3] += f1.y;
        acc[4] += f2.x; acc[5] += f2.y; acc[6] += f3.x; acc[7] += f3.y;
    }
    uint4 u;
    u.x = h2u(__float22half2_rn(make_float2(acc[0], acc[1])));
    u.y = h2u(__float22half2_rn(make_float2(acc[2], acc[3])));
    u.z = h2u(__float22half2_rn(make_float2(acc[4], acc[5])));
    u.w = h2u(__float22half2_rn(make_float2(acc[6], acc[7])));
    *(uint4*)(d_hh + (size_t)n * 256 + lane * 8) = u;

    // attention logits via S table: sum over the 6 rows (lanes 0..5 hold one each)
    float4 sv = make_float4(0.f, 0.f, 0.f, 0.f);
    if (lane < 6) sv = __ldg((const float4*)d_S + (c_voff[lane] + xv));
#pragma unroll
    for (int o = 1; o < 8; o <<= 1) {
        sv.x += __shfl_xor_sync(FULL, sv.x, o);
        sv.y += __shfl_xor_sync(FULL, sv.y, o);
        sv.z += __shfl_xor_sync(FULL, sv.z, o);
        sv.w += __shfl_xor_sync(FULL, sv.w, o);
    }
    if (lane == 0) {
        ((float2*)d_als)[n] = make_float2(sv.x, sv.y);
        ((float2*)d_ald)[n] = make_float2(sv.z, sv.w);
    }
}

// ---------------- CSR build ----------------
__global__ void k_hist(const int* __restrict__ ei) {
    int t = blockIdx.x * blockDim.x + threadIdx.x;
    if (t < EE) atomicAdd(&d_deg[gi(ei, EE + t, d_i64)], 1);
}
__global__ void k_scan1() {
    __shared__ int ws[32];
    int i = blockIdx.x * 1024 + threadIdx.x;
    int lane = threadIdx.x & 31, w = threadIdx.x >> 5;
    int x = (i < NN) ? d_deg[i] : 0;
#pragma unroll
    for (int o = 1; o < 32; o <<= 1) { int y = __shfl_up_sync(FULL, x, o); if (lane >= o) x += y; }
    if (lane == 31) ws[w] = x;
    __syncthreads();
    if (w == 0) {
        int t = ws[lane];
#pragma unroll
        for (int o = 1; o < 32; o <<= 1) { int y = __shfl_up_sync(FULL, t, o); if (lane >= o) t += y; }
        ws[lane] = t;
    }
    __syncthreads();
    x += (w > 0) ? ws[w - 1] : 0;
    if (i < NN) d_incl[i] = x;
    if (threadIdx.x == 1023) d_bsum[blockIdx.x] = x;
}
__global__ void k_scan23() {
    __shared__ int off_s;
    int tid = threadIdx.x;
    if (tid < 32) {
        int v = 0;
        for (int b = tid; b < blockIdx.x; b += 32) v += d_bsum[b];
        v = warpSumI(v);
        if (tid == 0) off_s = v;
    }
    __syncthreads();
    int i = blockIdx.x * 1024 + tid;
    if (i < NN) {
        int e = d_incl[i] - d_deg[i] + off_s;
        d_ptr[i] = e;
        d_pos[i] = e;
    }
    if (i == 0) d_ptr[NN] = ET;
}
__global__ void k_scatter(const int* __restrict__ ei) {
    int t = blockIdx.x * blockDim.x + threadIdx.x;
    if (t >= ET) return;
    int m64 = d_i64;
    int s, d;
    if (t < EE) { s = gi(ei, t, m64); d = gi(ei, EE + t, m64); }
    else { s = d = t - EE; }
    d_srcs[atomicAdd(&d_pos[d], 1)] = s;
}

// ---------------- HMMA layer-2 GEMM + fused als/ald ----------------
__global__ void k_hmma2(const __half* __restrict__ A, const unsigned* __restrict__ Bp,
                        const float* __restrict__ as_, const float* __restrict__ ad_, int M) {
    constexpr int NT = 32, NTW = 16;
    __shared__ __half As[64 * 136];
    int tid = threadIdx.x;
    int wid = tid >> 5, lane = tid & 31;
    int wm = wid >> 1, wn = wid & 1;
    int row0 = blockIdx.x * 64;

    {
        const uint4* Ag = (const uint4*)(A + (size_t)row0 * 128);
        uint4* Asm = (uint4*)As;
#pragma unroll
        for (int u = 0; u < 4; u++) {
            int f = tid + 256 * u;
            int r = f >> 4, c4 = f & 15;
            uint4 v = make_uint4(0, 0, 0, 0);
            if (row0 + r < M) v = __ldg(Ag + f);
            Asm[r * 17 + c4] = v;
        }
    }
    __syncthreads();

    float acc[NTW][4];
#pragma unroll
    for (int t = 0; t < NTW; t++) acc[t][0] = acc[t][1] = acc[t][2] = acc[t][3] = 0.f;
    int mrow = wm * 16;
    int arow = lane >> 2, acol = (lane & 3) * 2;
    const __half* Ab0 = As + (mrow + arow) * 136;
    const __half* Ab1 = As + (mrow + arow + 8) * 136;

#pragma unroll
    for (int kk = 0; kk < 8; kk++) {
        unsigned a0 = *(const unsigned*)(Ab0 + kk * 16 + acol);
        unsigned a1 = *(const unsigned*)(Ab1 + kk * 16 + acol);
        unsigned a2 = *(const unsigned*)(Ab0 + kk * 16 + acol + 8);
        unsigned a3 = *(const unsigned*)(Ab1 + kk * 16 + acol + 8);
#pragma unroll
        for (int t = 0; t < NTW; t++) {
            int nt = wn * NTW + t;
            uint2 b = __ldg((const uint2*)Bp + (kk * NT + nt) * 32 + lane);
            asm volatile(
                "mma.sync.aligned.m16n8k16.row.col.f32.f16.f16.f32 "
                "{%0,%1,%2,%3}, {%4,%5,%6,%7}, {%8,%9}, {%0,%1,%2,%3};"
                : "+f"(acc[t][0]), "+f"(acc[t][1]), "+f"(acc[t][2]), "+f"(acc[t][3])
                : "r"(a0), "r"(a1), "r"(a2), "r"(a3), "r"(b.x), "r"(b.y));
        }
    }

    int grow = row0 + mrow + arow;
    int coff = wn * 128 + (lane & 3) * 2;
    const float* S = as_ + wn * 128;
    const float* D = ad_ + wn * 128;
    float s0p = 0.f, d0p = 0.f, s1p = 0.f, d1p = 0.f;
#pragma unroll
    for (int t = 0; t < NTW; t++) {
        int lc = (lane & 3) * 2 + t * 8;
        float sa = __ldg(&S[lc]), sb = __ldg(&S[lc + 1]);
        float da = __ldg(&D[lc]), db = __ldg(&D[lc + 1]);
        s0p += acc[t][0] * sa + acc[t][1] * sb;
        d0p += acc[t][0] * da + acc[t][1] * db;
        s1p += acc[t][2] * sa + acc[t][3] * sb;
        d1p += acc[t][2] * da + acc[t][3] * db;
        int col = coff + t * 8;
        if (grow < M)
            *(__half2*)(d_hh + (size_t)grow * 256 + col) =
                __float22half2_rn(make_float2(acc[t][0], acc[t][1]));
        if (grow + 8 < M)
            *(__half2*)(d_hh + (size_t)(grow + 8) * 256 + col) =
                __float22half2_rn(make_float2(acc[t][2], acc[t][3]));
    }
#pragma unroll
    for (int o = 1; o < 4; o <<= 1) {
        s0p += __shfl_xor_sync(FULL, s0p, o);
        d0p += __shfl_xor_sync(FULL, d0p, o);
        s1p += __shfl_xor_sync(FULL, s1p, o);
        d1p += __shfl_xor_sync(FULL, d1p, o);
    }
    if ((lane & 3) == 0) {
        if (grow < M)     { d_als[grow * 2 + wn] = s0p * LOG2E;       d_ald[grow * 2 + wn] = d0p * LOG2E; }
        if (grow + 8 < M) { d_als[(grow + 8) * 2 + wn] = s1p * LOG2E; d_ald[(grow + 8) * 2 + wn] = d1p * LOG2E; }
    }
}

// ---------------- HMMA gate GEMM: fused BN+relu+dot(gw2)+exp+graph-sum ----------------
__global__ void k_hmmaG(const __half* __restrict__ A, const unsigned* __restrict__ Bp,
                        const float* __restrict__ gw2, const float* __restrict__ gb2,
                        const int* __restrict__ batch, int M) {
    constexpr int NT = 16, NTW = 8;
    __shared__ __half As[64 * 136];
    __shared__ float slog[64];
    int tid = threadIdx.x;
    int wid = tid >> 5, lane = tid & 31;
    int wm = wid >> 1, wn = wid & 1;
    int row0 = blockIdx.x * 64;

    if (tid < 64) slog[tid] = 0.f;
    {
        const uint4* Ag = (const uint4*)(A + (size_t)row0 * 128);
        uint4* Asm = (uint4*)As;
#pragma unroll
        for (int u = 0; u < 4; u++) {
            int f = tid + 256 * u;
            int r = f >> 4, c4 = f & 15;
            uint4 v = make_uint4(0, 0, 0, 0);
            if (row0 + r < M) v = __ldg(Ag + f);
            Asm[r * 17 + c4] = v;
        }
    }
    __syncthreads();

    float acc[NTW][4];
#pragma unroll
    for (int t = 0; t < NTW; t++) acc[t][0] = acc[t][1] = acc[t][2] = acc[t][3] = 0.f;
    int mrow = wm * 16;
    int arow = lane >> 2, acol = (lane & 3) * 2;
    const __half* Ab0 = As + (mrow + arow) * 136;
    const __half* Ab1 = As + (mrow + arow + 8) * 136;

#pragma unroll
    for (int kk = 0; kk < 8; kk++) {
        unsigned a0 = *(const unsigned*)(Ab0 + kk * 16 + acol);
        unsigned a1 = *(const unsigned*)(Ab1 + kk * 16 + acol);
        unsigned a2 = *(const unsigned*)(Ab0 + kk * 16 + acol + 8);
        unsigned a3 = *(const unsigned*)(Ab1 + kk * 16 + acol + 8);
#pragma unroll
        for (int t = 0; t < NTW; t++) {
            int nt = wn * NTW + t;
            uint2 b = __ldg((const uint2*)Bp + (kk * NT + nt) * 32 + lane);
            asm volatile(
                "mma.sync.aligned.m16n8k16.row.col.f32.f16.f16.f32 "
                "{%0,%1,%2,%3}, {%4,%5,%6,%7}, {%8,%9}, {%0,%1,%2,%3};"
                : "+f"(acc[t][0]), "+f"(acc[t][1]), "+f"(acc[t][2]), "+f"(acc[t][3])
                : "r"(a0), "r"(a1), "r"(a2), "r"(a3), "r"(b.x), "r"(b.y));
        }
    }

    float p0 = 0.f, p1 = 0.f;
#pragma unroll
    for (int t = 0; t < NTW; t++) {
        int c = wn * 64 + (lane & 3) * 2 + t * 8;
        float A0 = d_gA[c], A1 = d_gA[c + 1];
        float B0 = d_gB[c], B1 = d_gB[c + 1];
        float w0 = __ldg(&gw2[c]), w1 = __ldg(&gw2[c + 1]);
        float v;
        v = fmaf(acc[t][0], A0, B0); v = v > 0.f ? v : 0.f; p0 = fmaf(v, w0, p0);
        v = fmaf(acc[t][1], A1, B1); v = v > 0.f ? v : 0.f; p0 = fmaf(v, w1, p0);
        v = fmaf(acc[t][2], A0, B0); v = v > 0.f ? v : 0.f; p1 = fmaf(v, w0, p1);
        v = fmaf(acc[t][3], A1, B1); v = v > 0.f ? v : 0.f; p1 = fmaf(v, w1, p1);
    }
#pragma unroll
    for (int o = 1; o < 4; o <<= 1) {
        p0 += __shfl_xor_sync(FULL, p0, o);
        p1 += __shfl_xor_sync(FULL, p1, o);
    }
    int r0 = mrow + arow;
    if ((lane & 3) == 0) {
        atomicAdd(&slog[r0], p0);
        atomicAdd(&slog[r0 + 8], p1);
    }
    __syncthreads();
    if (tid < 64) {
        int n = row0 + tid;
        if (n < M) {
            float e = __expf(slog[tid] + __ldg(gb2));
            d_eg[n] = e;
            atomicAdd(&d_gs[gi(batch, n, d_i64)], e);
        }
    }
}

// ---------------- fused GAT: R11 pipelined half gather, warp per dst ----------------
__global__ void k_gat(const float* __restrict__ bias, __half* __restrict__ oh) {
    int n = blockIdx.x * 8 + (threadIdx.x >> 5);
    int lane = threadIdx.x & 31;
    if (n >= NN) return;
    int p0 = d_ptr[n], p1 = d_ptr[n + 1];
    float2 adv = ((const float2*)d_ald)[n];
    int head = lane >> 4;
    const float2* ALS = (const float2*)d_als;

    float acc[8];
#pragma unroll
    for (int r = 0; r < 8; r++) acc[r] = 0.f;
    float s0 = 0.f, s1 = 0.f;

    // 1-ahead software pipeline (deg >= 1 guaranteed by self-loop)
    int sx = __ldg(&d_srcs[p0]);
    float2 a_n = __ldg(ALS + sx);
    uint4 q_n = __ldg((const uint4*)(d_hh + (size_t)sx * 256) + lane);

#pragma unroll 2
    for (int j = p0; j < p1; j++) {
        float2 a_c = a_n;
        uint4 q_c = q_n;
        int jn = j + 1;
        if (jn < p1) {
            int sv = __ldg(&d_srcs[jn]);
            a_n = __ldg(ALS + sv);
            q_n = __ldg((const uint4*)(d_hh + (size_t)sv * 256) + lane);
        }
        float e0 = a_c.x + adv.x; e0 = e0 > 0.f ? e0 : 0.2f * e0;
        float e1 = a_c.y + adv.y; e1 = e1 > 0.f ? e1 : 0.2f * e1;
        float w0 = ex2_(e0), w1 = ex2_(e1);
        s0 += w0; s1 += w1;
        float w = head ? w1 : w0;
        __half2* hp = (__half2*)&q_c;
        float2 f0 = __half22float2(hp[0]), f1 = __half22float2(hp[1]);
        float2 f2 = __half22float2(hp[2]), f3 = __half22float2(hp[3]);
        acc[0] = fmaf(w, f0.x, acc[0]); acc[1] = fmaf(w, f0.y, acc[1]);
        acc[2] = fmaf(w, f1.x, acc[2]); acc[3] = fmaf(w, f1.y, acc[3]);
        acc[4] = fmaf(w, f2.x, acc[4]); acc[5] = fmaf(w, f2.y, acc[5]);
        acc[6] = fmaf(w, f3.x, acc[6]); acc[7] = fmaf(w, f3.y, acc[7]);
    }
    float i0 = 0.5f / (s0 + 1e-16f), i1 = 0.5f / (s1 + 1e-16f);
    float o[8];
#pragma unroll
    for (int r = 0; r < 8; r++) {
        float other = __shfl_xor_sync(FULL, acc[r], 16);
        o[r] = head ? fmaf(other, i0, acc[r] * i1) : fmaf(acc[r], i0, other * i1);
    }
    if (lane < 16) {
        float4 b0 = __ldg((const float4*)bias + 2 * lane);
        float4 b1 = __ldg((const float4*)bias + 2 * lane + 1);
        uint4 u;
        u.x = h2u(__float22half2_rn(make_float2(sig_(o[0] + b0.x), sig_(o[1] + b0.y))));
        u.y = h2u(__float22half2_rn(make_float2(sig_(o[2] + b0.z), sig_(o[3] + b0.w))));
        u.z = h2u(__float22half2_rn(make_float2(sig_(o[4] + b1.x), sig_(o[5] + b1.y))));
        u.w = h2u(__float22half2_rn(make_float2(sig_(o[6] + b1.z), sig_(o[7] + b1.w))));
        *(uint4*)(oh + (size_t)n * 128 + 8 * lane) = u;
    }
}

// ---------------- pooling (last block also computes final output) ----------------
__global__ void k_pool(const int* __restrict__ batch,
                       const float* __restrict__ glw, const float* __restrict__ glb,
                       float* __restrict__ out) {
    int j = threadIdx.x;
    int n0 = blockIdx.x * 128;
    int n1 = min(n0 + 128, NN);
    int m64 = d_i64;
    float a = 0.f;
    int curg = gi(batch, n0, m64);
    for (int n = n0; n < n1; n++) {
        int b = gi(batch, n, m64);
        if (b != curg) {
            atomicAdd(&d_pooled[curg * 128 + j], a);
            a = 0.f;
            curg = b;
        }
        float gate = d_eg[n] / (d_gs[b] + 1e-16f);
        a = fmaf(gate, __half2float(__ldg(&d_o2h[(size_t)n * 128 + j])), a);
    }
    atomicAdd(&d_pooled[curg * 128 + j], a);

    // last-block finalization
    __shared__ int isLast;
    __threadfence();
    __syncthreads();
    if (j == 0) {
        int old = atomicAdd(&d_ctr, 1);
        isLast = (old == gridDim.x - 1);
        if (isLast) d_ctr = 0;   // reset for next graph replay
    }
    __syncthreads();
    if (isLast) {
        __threadfence();
        int w = j >> 5, lane = j & 31;
        for (int g = w * 32; g < w * 32 + 32; g++) {
            float p = d_pooled[g * 128 + lane] * __ldg(&glw[lane])
                    + d_pooled[g * 128 + lane + 32] * __ldg(&glw[lane + 32])
                    + d_pooled[g * 128 + lane + 64] * __ldg(&glw[lane + 64])
                    + d_pooled[g * 128 + lane + 96] * __ldg(&glw[lane + 96]);
            p = warpSum(p);
            if (lane == 0) out[g] = sig_(p + __ldg(glb));
        }
    }
}

// ---------------- launch ----------------
extern "C" void kernel_launch(void* const* d_in, const int* in_sizes, int n_in,
                              void* d_out, int out_size) {
    const int* x     = (const int*)d_in[0];
    const int* ei    = (const int*)d_in[1];
    const int* batch = (const int*)d_in[3];
    const float* emb0 = (const float*)d_in[4];
    const float* emb1 = (const float*)d_in[5];
    const float* emb2 = (const float*)d_in[6];
    const float* emb3 = (const float*)d_in[7];
    const float* emb4 = (const float*)d_in[8];
    const float* emb5 = (const float*)d_in[9];
    const float* W1  = (const float*)d_in[10];
    const float* as1 = (const float*)d_in[11];
    const float* ad1 = (const float*)d_in[12];
    const float* b1  = (const float*)d_in[13];
    const float* W2  = (const float*)d_in[14];
    const float* as2 = (const float*)d_in[15];
    const float* ad2 = (const float*)d_in[16];
    const float* b2  = (const float*)d_in[17];
    const float* gw1 = (const float*)d_in[18];
    const float* gb1 = (const float*)d_in[19];
    const float* bng = (const float*)d_in[20];
    const float* bnb = (const float*)d_in[21];
    const float* bnm = (const float*)d_in[22];
    const float* bnv = (const float*)d_in[23];
    const float* gw2 = (const float*)d_in[24];
    const float* gb2 = (const float*)d_in[25];
    const float* glw = (const float*)d_in[26];
    const float* glb = (const float*)d_in[27];
    float* out = (float*)d_out;

    __half* p_o1h; cudaGetSymbolAddress((void**)&p_o1h, d_o1h);
    __half* p_o2h; cudaGetSymbolAddress((void**)&p_o2h, d_o2h);
    unsigned* p_W2p;  cudaGetSymbolAddress((void**)&p_W2p, d_W2p);
    unsigned* p_gw1p; cudaGetSymbolAddress((void**)&p_gw1p, d_gw1p);

    const int gNODE = NN / 8;
    const int gEDGE = (ET + 255) / 256;
    const int gHM = (NN + 63) / 64;

    k_init0<<<512, 256>>>(ei, emb0, emb1, emb2, emb3, emb4, emb5, W1, W2,
                          gw1, gb1, bng, bnb, bnm, bnv);                 // 1
    k_hist<<<(EE + 255) / 256, 256>>>(ei);                               // 2
    k_S<<<1, 256>>>(as1, ad1);                                           // 3
    k_embed<<<gNODE, 256>>>(x);                                          // 4 <- profiled
    k_scan1<<<NB, 1024>>>();                                             // 5
    k_scan23<<<NB, 1024>>>();                                            // 6
    k_scatter<<<gEDGE, 256>>>(ei);                                       // 7

    k_gat<<<gNODE, 256>>>(b1, p_o1h);                                    // 8
    k_hmma2<<<gHM, 256>>>(p_o1h, p_W2p, as2, ad2, NN);                   // 9
    k_gat<<<gNODE, 256>>>(b2, p_o2h);                                    // 10

    k_hmmaG<<<gHM, 256>>>(p_o2h, p_gw1p, gw2, gb2, batch, NN);           // 11
    k_pool<<<(NN + 127) / 128, 128>>>(batch, glw, glb, out);             // 12

    (void)in_sizes; (void)n_in; (void)out_size;
}

// round 16
// speedup vs baseline: 1.1354x; 1.0317x over previous
#include <cuda_runtime.h>
#include <cuda_fp16.h>
#include <math.h>

#define NN 100000
#define EE 800000
#define ET (EE + NN)
#define GG 128
#define NB 98   /* ceil(NN/1024) */
#define FULL 0xffffffffu
#define LOG2E 1.4426950408889634f
#define HS 64.0f           /* h fp8 scale */
#define HSI (1.0f / 64.0f)

typedef unsigned long long ull;

// ---------------- scratch (static device memory) ----------------
__device__ ull d_hh8[(size_t)NN * 32];       // h fp8 e4m3, 256 B/row (25.6 MB, L2-resident)
__device__ __half d_o1h[(size_t)NN * 128];   // out1 fp16
__device__ __half d_o2h[(size_t)NN * 128];   // out2 fp16
__device__ float d_als[NN * 2], d_ald[NN * 2];   // pre-scaled by log2(e)
__device__ float d_eg[NN];
__device__ float d_gs[GG];
__device__ float d_pooled[GG * 128];
__device__ float d_T1[50 * 256];
__device__ __half d_T1h[50 * 256];           // fp16 copy for k_embed gather
__device__ float d_S[50 * 4];                // per-row (s0,s1,d0,d1) * LOG2E
__device__ unsigned d_W2p[8 * 32 * 32 * 2];  // prepacked B frags
__device__ unsigned d_gw1p[8 * 16 * 32 * 2];
__device__ float d_gA[128], d_gB[128];       // folded BN for gate
__device__ int d_deg[NN], d_incl[NN], d_ptr[NN + 1], d_pos[NN];
__device__ int d_srcs[ET];
__device__ int d_bsum[128];
__device__ int d_i64;
__device__ int d_ctr;                        // pool completion counter (self-resetting)

__constant__ int c_voff[6] = {0, 33, 38, 41, 45, 47};

// ---------------- helpers ----------------
__device__ __forceinline__ float sig_(float x) { return 1.f / (1.f + __expf(-x)); }
__device__ __forceinline__ float ex2_(float x) {
    float r;
    asm("ex2.approx.ftz.f32 %0, %1;" : "=f"(r) : "f"(x));
    return r;
}
__device__ __forceinline__ float warpSum(float v) {
#pragma unroll
    for (int o = 16; o; o >>= 1) v += __shfl_xor_sync(FULL, v, o);
    return v;
}
__device__ __forceinline__ int warpSumI(int v) {
#pragma unroll
    for (int o = 16; o; o >>= 1) v += __shfl_xor_sync(FULL, v, o);
    return v;
}
__device__ __forceinline__ float dot4(float4 a, float4 b) {
    return a.x * b.x + a.y * b.y + a.z * b.z + a.w * b.w;
}
__device__ __forceinline__ int gi(const int* __restrict__ p, int i, int m64) {
    return p[m64 ? (i << 1) : i];
}
__device__ __forceinline__ unsigned h2u(__half2 h) { return *(unsigned*)&h; }
// pack two floats -> e4m3x2 (a -> low byte, b -> high byte)
__device__ __forceinline__ unsigned short f2e8(float a, float b) {
    unsigned short r;
    asm("cvt.rn.satfinite.e4m3x2.f32 %0, %1, %2;" : "=h"(r) : "f"(b), "f"(a));
    return r;
}
// unpack e4m3x2 -> float2 (low byte -> .x)
__device__ __forceinline__ float2 e8tof2(unsigned short u) {
    unsigned hh;
    asm("cvt.rn.f16x2.e4m3x2 %0, %1;" : "=r"(hh) : "h"(u));
    return __half22float2(*(__half2*)&hh);
}

// ---------------- init0: detect + deg=1 + zeros + pack + T1 (fp32 & fp16) ----------------
__global__ void k_init0(const int* __restrict__ ei,
                        const float* __restrict__ e0, const float* __restrict__ e1,
                        const float* __restrict__ e2, const float* __restrict__ e3,
                        const float* __restrict__ e4, const float* __restrict__ e5,
                        const float* __restrict__ W1, const float* __restrict__ W2,
                        const float* __restrict__ gw1, const float* __restrict__ gb1,
                        const float* __restrict__ bng, const float* __restrict__ bnb,
                        const float* __restrict__ bnm, const float* __restrict__ bnv) {
    int i = blockIdx.x * 256 + threadIdx.x;
    if (i == 0)
        d_i64 = ((ei[1] | ei[3] | ei[5] | ei[7] | ei[9]) == 0) ? 1 : 0;
    if (i < NN) d_deg[i] = 1;
    if (i < GG * 128) d_pooled[i] = 0.f;
    if (i < GG) d_gs[i] = 0.f;
    if (i < 8192) {
        int lane = i & 31, nt = (i >> 5) & 31, kk = i >> 10;
        int k0 = kk * 16 + (lane & 3) * 2, n = nt * 8 + (lane >> 2);
        unsigned lo = h2u(__float22half2_rn(make_float2(W2[k0 * 256 + n],       W2[(k0 + 1) * 256 + n])));
        unsigned hi = h2u(__float22half2_rn(make_float2(W2[(k0 + 8) * 256 + n], W2[(k0 + 9) * 256 + n])));
        d_W2p[i * 2] = lo; d_W2p[i * 2 + 1] = hi;
    } else if (i < 8192 + 4096) {
        int u = i - 8192;
        int lane = u & 31, nt = (u >> 5) & 15, kk = u >> 9;
        int k0 = kk * 16 + (lane & 3) * 2, n = nt * 8 + (lane >> 2);
        unsigned lo = h2u(__float22half2_rn(make_float2(gw1[k0 * 128 + n],       gw1[(k0 + 1) * 128 + n])));
        unsigned hi = h2u(__float22half2_rn(make_float2(gw1[(k0 + 8) * 128 + n], gw1[(k0 + 9) * 128 + n])));
        d_gw1p[u * 2] = lo; d_gw1p[u * 2 + 1] = hi;
    } else if (i < 8192 + 4096 + 128) {
        int j = i - 8192 - 4096;
        float a = rsqrtf(bnv[j] + 1e-5f) * bng[j];
        d_gA[j] = a;
        d_gB[j] = (gb1[j] - bnm[j]) * a + bnb[j];
    }
    // T1 (blocks 0..49)
    int row = blockIdx.x;
    if (row < 50) {
        int j = threadIdx.x;
        int t, v;
        if (row < 33)      { t = 0; v = row; }
        else if (row < 38) { t = 1; v = row - 33; }
        else if (row < 41) { t = 2; v = row - 38; }
        else if (row < 45) { t = 3; v = row - 41; }
        else if (row < 47) { t = 4; v = row - 45; }
        else               { t = 5; v = row - 47; }
        const float* emb = (t == 0) ? e0 : (t == 1) ? e1 : (t == 2) ? e2 : (t == 3) ? e3 : (t == 4) ? e4 : e5;
        float acc = 0.f;
#pragma unroll 8
        for (int c = 0; c < 64; c++) acc = fmaf(emb[v * 64 + c], W1[(size_t)(t * 64 + c) * 256 + j], acc);
        d_T1[row * 256 + j] = acc;
        d_T1h[row * 256 + j] = __float2half_rn(acc);
    }
}

// ---------------- S table ----------------
__global__ void k_S(const float* __restrict__ as_, const float* __restrict__ ad_) {
    int t = threadIdx.x;
    if (t >= 200) return;
    int row = t >> 2, q = t & 3, h = q & 1;
    const float* a = (q < 2) ? as_ : ad_;
    float acc = 0.f;
#pragma unroll 8
    for (int c = 0; c < 128; c++)
        acc = fmaf(d_T1[row * 256 + h * 128 + c], a[h * 128 + c], acc);
    d_S[row * 4 + q] = acc * LOG2E;
}

// ---------------- h1 embed (fp16 T1 gather, fp8 store) + table-based logits ----------------
__global__ void k_embed(const int* __restrict__ x) {
    int n = blockIdx.x * 8 + (threadIdx.x >> 5);
    int lane = threadIdx.x & 31;
    if (n >= NN) return;
    int m64 = d_i64;
    int xv = 0;
    if (lane < 6) xv = gi(x, n * 6 + lane, m64);
    int rows[6];
#pragma unroll
    for (int i = 0; i < 6; i++) rows[i] = c_voff[i] + __shfl_sync(FULL, xv, i);

    float acc[8];
#pragma unroll
    for (int r = 0; r < 8; r++) acc[r] = 0.f;
#pragma unroll
    for (int i = 0; i < 6; i++) {
        uint4 q = *(const uint4*)(d_T1h + rows[i] * 256 + lane * 8);
        __half2* hp = (__half2*)&q;
        float2 f0 = __half22float2(hp[0]), f1 = __half22float2(hp[1]);
        float2 f2 = __half22float2(hp[2]), f3 = __half22float2(hp[3]);
        acc[0] += f0.x; acc[1] += f0.y; acc[2] += f1.x; acc[3] += f1.y;
        acc[4] += f2.x; acc[5] += f2.y; acc[6] += f3.x; acc[7] += f3.y;
    }
    // store fp8 (scaled by HS): 8 values = uint2
    uint2 u;
    u.x = (unsigned)f2e8(acc[0] * HS, acc[1] * HS) | ((unsigned)f2e8(acc[2] * HS, acc[3] * HS) << 16);
    u.y = (unsigned)f2e8(acc[4] * HS, acc[5] * HS) | ((unsigned)f2e8(acc[6] * HS, acc[7] * HS) << 16);
    *((uint2*)((unsigned char*)d_hh8 + (size_t)n * 256) + lane) = u;

    // attention logits via S table
    float4 sv = make_float4(0.f, 0.f, 0.f, 0.f);
    if (lane < 6) sv = __ldg((const float4*)d_S + (c_voff[lane] + xv));
#pragma unroll
    for (int o = 1; o < 8; o <<= 1) {
        sv.x += __shfl_xor_sync(FULL, sv.x, o);
        sv.y += __shfl_xor_sync(FULL, sv.y, o);
        sv.z += __shfl_xor_sync(FULL, sv.z, o);
        sv.w += __shfl_xor_sync(FULL, sv.w, o);
    }
    if (lane == 0) {
        ((float2*)d_als)[n] = make_float2(sv.x, sv.y);
        ((float2*)d_ald)[n] = make_float2(sv.z, sv.w);
    }
}

// ---------------- CSR build ----------------
__global__ void k_hist(const int* __restrict__ ei) {
    int t = blockIdx.x * blockDim.x + threadIdx.x;
    if (t < EE) atomicAdd(&d_deg[gi(ei, EE + t, d_i64)], 1);
}
__global__ void k_scan1() {
    __shared__ int ws[32];
    int i = blockIdx.x * 1024 + threadIdx.x;
    int lane = threadIdx.x & 31, w = threadIdx.x >> 5;
    int x = (i < NN) ? d_deg[i] : 0;
#pragma unroll
    for (int o = 1; o < 32; o <<= 1) { int y = __shfl_up_sync(FULL, x, o); if (lane >= o) x += y; }
    if (lane == 31) ws[w] = x;
    __syncthreads();
    if (w == 0) {
        int t = ws[lane];
#pragma unroll
        for (int o = 1; o < 32; o <<= 1) { int y = __shfl_up_sync(FULL, t, o); if (lane >= o) t += y; }
        ws[lane] = t;
    }
    __syncthreads();
    x += (w > 0) ? ws[w - 1] : 0;
    if (i < NN) d_incl[i] = x;
    if (threadIdx.x == 1023) d_bsum[blockIdx.x] = x;
}
__global__ void k_scan23() {
    __shared__ int off_s;
    int tid = threadIdx.x;
    if (tid < 32) {
        int v = 0;
        for (int b = tid; b < blockIdx.x; b += 32) v += d_bsum[b];
        v = warpSumI(v);
        if (tid == 0) off_s = v;
    }
    __syncthreads();
    int i = blockIdx.x * 1024 + tid;
    if (i < NN) {
        int e = d_incl[i] - d_deg[i] + off_s;
        d_ptr[i] = e;
        d_pos[i] = e;
    }
    if (i == 0) d_ptr[NN] = ET;
}
__global__ void k_scatter(const int* __restrict__ ei) {
    int t = blockIdx.x * blockDim.x + threadIdx.x;
    if (t >= ET) return;
    int m64 = d_i64;
    int s, d;
    if (t < EE) { s = gi(ei, t, m64); d = gi(ei, EE + t, m64); }
    else { s = d = t - EE; }
    d_srcs[atomicAdd(&d_pos[d], 1)] = s;
}

// ---------------- HMMA layer-2 GEMM (fp8 h out) + fused als/ald ----------------
__global__ void k_hmma2(const __half* __restrict__ A, const unsigned* __restrict__ Bp,
                        const float* __restrict__ as_, const float* __restrict__ ad_, int M) {
    constexpr int NT = 32, NTW = 16;
    __shared__ __half As[64 * 136];
    int tid = threadIdx.x;
    int wid = tid >> 5, lane = tid & 31;
    int wm = wid >> 1, wn = wid & 1;
    int row0 = blockIdx.x * 64;

    {
        const uint4* Ag = (const uint4*)(A + (size_t)row0 * 128);
        uint4* Asm = (uint4*)As;
#pragma unroll
        for (int u = 0; u < 4; u++) {
            int f = tid + 256 * u;
            int r = f >> 4, c4 = f & 15;
            uint4 v = make_uint4(0, 0, 0, 0);
            if (row0 + r < M) v = __ldg(Ag + f);
            Asm[r * 17 + c4] = v;
        }
    }
    __syncthreads();

    float acc[NTW][4];
#pragma unroll
    for (int t = 0; t < NTW; t++) acc[t][0] = acc[t][1] = acc[t][2] = acc[t][3] = 0.f;
    int mrow = wm * 16;
    int arow = lane >> 2, acol = (lane & 3) * 2;
    const __half* Ab0 = As + (mrow + arow) * 136;
    const __half* Ab1 = As + (mrow + arow + 8) * 136;

#pragma unroll
    for (int kk = 0; kk < 8; kk++) {
        unsigned a0 = *(const unsigned*)(Ab0 + kk * 16 + acol);
        unsigned a1 = *(const unsigned*)(Ab1 + kk * 16 + acol);
        unsigned a2 = *(const unsigned*)(Ab0 + kk * 16 + acol + 8);
        unsigned a3 = *(const unsigned*)(Ab1 + kk * 16 + acol + 8);
#pragma unroll
        for (int t = 0; t < NTW; t++) {
            int nt = wn * NTW + t;
            uint2 b = __ldg((const uint2*)Bp + (kk * NT + nt) * 32 + lane);
            asm volatile(
                "mma.sync.aligned.m16n8k16.row.col.f32.f16.f16.f32 "
                "{%0,%1,%2,%3}, {%4,%5,%6,%7}, {%8,%9}, {%0,%1,%2,%3};"
                : "+f"(acc[t][0]), "+f"(acc[t][1]), "+f"(acc[t][2]), "+f"(acc[t][3])
                : "r"(a0), "r"(a1), "r"(a2), "r"(a3), "r"(b.x), "r"(b.y));
        }
    }

    int grow = row0 + mrow + arow;
    int coff = wn * 128 + (lane & 3) * 2;
    const float* S = as_ + wn * 128;
    const float* D = ad_ + wn * 128;
    unsigned char* H8 = (unsigned char*)d_hh8;
    float s0p = 0.f, d0p = 0.f, s1p = 0.f, d1p = 0.f;
#pragma unroll
    for (int t = 0; t < NTW; t++) {
        int lc = (lane & 3) * 2 + t * 8;
        float sa = __ldg(&S[lc]), sb = __ldg(&S[lc + 1]);
        float da = __ldg(&D[lc]), db = __ldg(&D[lc + 1]);
        s0p += acc[t][0] * sa + acc[t][1] * sb;
        d0p += acc[t][0] * da + acc[t][1] * db;
        s1p += acc[t][2] * sa + acc[t][3] * sb;
        d1p += acc[t][2] * da + acc[t][3] * db;
        int col = coff + t * 8;
        if (grow < M)
            *(unsigned short*)(H8 + (size_t)grow * 256 + col) = f2e8(acc[t][0] * HS, acc[t][1] * HS);
        if (grow + 8 < M)
            *(unsigned short*)(H8 + (size_t)(grow + 8) * 256 + col) = f2e8(acc[t][2] * HS, acc[t][3] * HS);
    }
#pragma unroll
    for (int o = 1; o < 4; o <<= 1) {
        s0p += __shfl_xor_sync(FULL, s0p, o);
        d0p += __shfl_xor_sync(FULL, d0p, o);
        s1p += __shfl_xor_sync(FULL, s1p, o);
        d1p += __shfl_xor_sync(FULL, d1p, o);
    }
    if ((lane & 3) == 0) {
        if (grow < M)     { d_als[grow * 2 + wn] = s0p * LOG2E;       d_ald[grow * 2 + wn] = d0p * LOG2E; }
        if (grow + 8 < M) { d_als[(grow + 8) * 2 + wn] = s1p * LOG2E; d_ald[(grow + 8) * 2 + wn] = d1p * LOG2E; }
    }
}

// ---------------- HMMA gate GEMM: fused BN+relu+dot(gw2)+exp+graph-sum ----------------
__global__ void k_hmmaG(const __half* __restrict__ A, const unsigned* __restrict__ Bp,
                        const float* __restrict__ gw2, const float* __restrict__ gb2,
                        const int* __restrict__ batch, int M) {
    constexpr int NT = 16, NTW = 8;
    __shared__ __half As[64 * 136];
    __shared__ float slog[64];
    int tid = threadIdx.x;
    int wid = tid >> 5, lane = tid & 31;
    int wm = wid >> 1, wn = wid & 1;
    int row0 = blockIdx.x * 64;

    if (tid < 64) slog[tid] = 0.f;
    {
        const uint4* Ag = (const uint4*)(A + (size_t)row0 * 128);
        uint4* Asm = (uint4*)As;
#pragma unroll
        for (int u = 0; u < 4; u++) {
            int f = tid + 256 * u;
            int r = f >> 4, c4 = f & 15;
            uint4 v = make_uint4(0, 0, 0, 0);
            if (row0 + r < M) v = __ldg(Ag + f);
            Asm[r * 17 + c4] = v;
        }
    }
    __syncthreads();

    float acc[NTW][4];
#pragma unroll
    for (int t = 0; t < NTW; t++) acc[t][0] = acc[t][1] = acc[t][2] = acc[t][3] = 0.f;
    int mrow = wm * 16;
    int arow = lane >> 2, acol = (lane & 3) * 2;
    const __half* Ab0 = As + (mrow + arow) * 136;
    const __half* Ab1 = As + (mrow + arow + 8) * 136;

#pragma unroll
    for (int kk = 0; kk < 8; kk++) {
        unsigned a0 = *(const unsigned*)(Ab0 + kk * 16 + acol);
        unsigned a1 = *(const unsigned*)(Ab1 + kk * 16 + acol);
        unsigned a2 = *(const unsigned*)(Ab0 + kk * 16 + acol + 8);
        unsigned a3 = *(const unsigned*)(Ab1 + kk * 16 + acol + 8);
#pragma unroll
        for (int t = 0; t < NTW; t++) {
            int nt = wn * NTW + t;
            uint2 b = __ldg((const uint2*)Bp + (kk * NT + nt) * 32 + lane);
            asm volatile(
                "mma.sync.aligned.m16n8k16.row.col.f32.f16.f16.f32 "
                "{%0,%1,%2,%3}, {%4,%5,%6,%7}, {%8,%9}, {%0,%1,%2,%3};"
                : "+f"(acc[t][0]), "+f"(acc[t][1]), "+f"(acc[t][2]), "+f"(acc[t][3])
                : "r"(a0), "r"(a1), "r"(a2), "r"(a3), "r"(b.x), "r"(b.y));
        }
    }

    float p0 = 0.f, p1 = 0.f;
#pragma unroll
    for (int t = 0; t < NTW; t++) {
        int c = wn * 64 + (lane & 3) * 2 + t * 8;
        float A0 = d_gA[c], A1 = d_gA[c + 1];
        float B0 = d_gB[c], B1 = d_gB[c + 1];
        float w0 = __ldg(&gw2[c]), w1 = __ldg(&gw2[c + 1]);
        float v;
        v = fmaf(acc[t][0], A0, B0); v = v > 0.f ? v : 0.f; p0 = fmaf(v, w0, p0);
        v = fmaf(acc[t][1], A1, B1); v = v > 0.f ? v : 0.f; p0 = fmaf(v, w1, p0);
        v = fmaf(acc[t][2], A0, B0); v = v > 0.f ? v : 0.f; p1 = fmaf(v, w0, p1);
        v = fmaf(acc[t][3], A1, B1); v = v > 0.f ? v : 0.f; p1 = fmaf(v, w1, p1);
    }
#pragma unroll
    for (int o = 1; o < 4; o <<= 1) {
        p0 += __shfl_xor_sync(FULL, p0, o);
        p1 += __shfl_xor_sync(FULL, p1, o);
    }
    int r0 = mrow + arow;
    if ((lane & 3) == 0) {
        atomicAdd(&slog[r0], p0);
        atomicAdd(&slog[r0 + 8], p1);
    }
    __syncthreads();
    if (tid < 64) {
        int n = row0 + tid;
        if (n < M) {
            float e = __expf(slog[tid] + __ldg(gb2));
            d_eg[n] = e;
            atomicAdd(&d_gs[gi(batch, n, d_i64)], e);
        }
    }
}

// ---------------- fused GAT: R11 pipeline, fp8 gather (uint2/lane/edge) ----------------
__global__ void k_gat(const float* __restrict__ bias, __half* __restrict__ oh) {
    int n = blockIdx.x * 8 + (threadIdx.x >> 5);
    int lane = threadIdx.x & 31;
    if (n >= NN) return;
    int p0 = d_ptr[n], p1 = d_ptr[n + 1];
    float2 adv = ((const float2*)d_ald)[n];
    int head = lane >> 4;
    const float2* ALS = (const float2*)d_als;
    const unsigned char* H8 = (const unsigned char*)d_hh8;

    float acc[8];
#pragma unroll
    for (int r = 0; r < 8; r++) acc[r] = 0.f;
    float s0 = 0.f, s1 = 0.f;

    // 1-ahead software pipeline (deg >= 1 guaranteed by self-loop)
    int sx = __ldg(&d_srcs[p0]);
    float2 a_n = __ldg(ALS + sx);
    uint2 q_n = __ldg((const uint2*)(H8 + (size_t)sx * 256) + lane);

#pragma unroll 2
    for (int j = p0; j < p1; j++) {
        float2 a_c = a_n;
        uint2 q_c = q_n;
        int jn = j + 1;
        if (jn < p1) {
            int sv = __ldg(&d_srcs[jn]);
            a_n = __ldg(ALS + sv);
            q_n = __ldg((const uint2*)(H8 + (size_t)sv * 256) + lane);
        }
        float e0 = a_c.x + adv.x; e0 = e0 > 0.f ? e0 : 0.2f * e0;
        float e1 = a_c.y + adv.y; e1 = e1 > 0.f ? e1 : 0.2f * e1;
        float w0 = ex2_(e0), w1 = ex2_(e1);
        s0 += w0; s1 += w1;
        float w = head ? w1 : w0;
        float2 f0 = e8tof2((unsigned short)(q_c.x & 0xffff));
        float2 f1 = e8tof2((unsigned short)(q_c.x >> 16));
        float2 f2 = e8tof2((unsigned short)(q_c.y & 0xffff));
        float2 f3 = e8tof2((unsigned short)(q_c.y >> 16));
        acc[0] = fmaf(w, f0.x, acc[0]); acc[1] = fmaf(w, f0.y, acc[1]);
        acc[2] = fmaf(w, f1.x, acc[2]); acc[3] = fmaf(w, f1.y, acc[3]);
        acc[4] = fmaf(w, f2.x, acc[4]); acc[5] = fmaf(w, f2.y, acc[5]);
        acc[6] = fmaf(w, f3.x, acc[6]); acc[7] = fmaf(w, f3.y, acc[7]);
    }
    float i0 = (0.5f * HSI) / (s0 + 1e-16f), i1 = (0.5f * HSI) / (s1 + 1e-16f);
    float o[8];
#pragma unroll
    for (int r = 0; r < 8; r++) {
        float other = __shfl_xor_sync(FULL, acc[r], 16);
        o[r] = head ? fmaf(other, i0, acc[r] * i1) : fmaf(acc[r], i0, other * i1);
    }
    if (lane < 16) {
        float4 b0 = __ldg((const float4*)bias + 2 * lane);
        float4 b1 = __ldg((const float4*)bias + 2 * lane + 1);
        uint4 u;
        u.x = h2u(__float22half2_rn(make_float2(sig_(o[0] + b0.x), sig_(o[1] + b0.y))));
        u.y = h2u(__float22half2_rn(make_float2(sig_(o[2] + b0.z), sig_(o[3] + b0.w))));
        u.z = h2u(__float22half2_rn(make_float2(sig_(o[4] + b1.x), sig_(o[5] + b1.y))));
        u.w = h2u(__float22half2_rn(make_float2(sig_(o[6] + b1.z), sig_(o[7] + b1.w))));
        *(uint4*)(oh + (size_t)n * 128 + 8 * lane) = u;
    }
}

// ---------------- pooling (last block also computes final output) ----------------
__global__ void k_pool(const int* __restrict__ batch,
                       const float* __restrict__ glw, const float* __restrict__ glb,
                       float* __restrict__ out) {
    int j = threadIdx.x;
    int n0 = blockIdx.x * 128;
    int n1 = min(n0 + 128, NN);
    int m64 = d_i64;
    float a = 0.f;
    int curg = gi(batch, n0, m64);
    for (int n = n0; n < n1; n++) {
        int b = gi(batch, n, m64);
        if (b != curg) {
            atomicAdd(&d_pooled[curg * 128 + j], a);
            a = 0.f;
            curg = b;
        }
        float gate = d_eg[n] / (d_gs[b] + 1e-16f);
        a = fmaf(gate, __half2float(__ldg(&d_o2h[(size_t)n * 128 + j])), a);
    }
    atomicAdd(&d_pooled[curg * 128 + j], a);

    __shared__ int isLast;
    __threadfence();
    __syncthreads();
    if (j == 0) {
        int old = atomicAdd(&d_ctr, 1);
        isLast = (old == gridDim.x - 1);
        if (isLast) d_ctr = 0;
    }
    __syncthreads();
    if (isLast) {
        __threadfence();
        int w = j >> 5, lane = j & 31;
        for (int g = w * 32; g < w * 32 + 32; g++) {
            float p = d_pooled[g * 128 + lane] * __ldg(&glw[lane])
                    + d_pooled[g * 128 + lane + 32] * __ldg(&glw[lane + 32])
                    + d_pooled[g * 128 + lane + 64] * __ldg(&glw[lane + 64])
                    + d_pooled[g * 128 + lane + 96] * __ldg(&glw[lane + 96]);
            p = warpSum(p);
            if (lane == 0) out[g] = sig_(p + __ldg(glb));
        }
    }
}

// ---------------- launch ----------------
extern "C" void kernel_launch(void* const* d_in, const int* in_sizes, int n_in,
                              void* d_out, int out_size) {
    const int* x     = (const int*)d_in[0];
    const int* ei    = (const int*)d_in[1];
    const int* batch = (const int*)d_in[3];
    const float* emb0 = (const float*)d_in[4];
    const float* emb1 = (const float*)d_in[5];
    const float* emb2 = (const float*)d_in[6];
    const float* emb3 = (const float*)d_in[7];
    const float* emb4 = (const float*)d_in[8];
    const float* emb5 = (const float*)d_in[9];
    const float* W1  = (const float*)d_in[10];
    const float* as1 = (const float*)d_in[11];
    const float* ad1 = (const float*)d_in[12];
    const float* b1  = (const float*)d_in[13];
    const float* W2  = (const float*)d_in[14];
    const float* as2 = (const float*)d_in[15];
    const float* ad2 = (const float*)d_in[16];
    const float* b2  = (const float*)d_in[17];
    const float* gw1 = (const float*)d_in[18];
    const float* gb1 = (const float*)d_in[19];
    const float* bng = (const float*)d_in[20];
    const float* bnb = (const float*)d_in[21];
    const float* bnm = (const float*)d_in[22];
    const float* bnv = (const float*)d_in[23];
    const float* gw2 = (const float*)d_in[24];
    const float* gb2 = (const float*)d_in[25];
    const float* glw = (const float*)d_in[26];
    const float* glb = (const float*)d_in[27];
    float* out = (float*)d_out;

    __half* p_o1h; cudaGetSymbolAddress((void**)&p_o1h, d_o1h);
    __half* p_o2h; cudaGetSymbolAddress((void**)&p_o2h, d_o2h);
    unsigned* p_W2p;  cudaGetSymbolAddress((void**)&p_W2p, d_W2p);
    unsigned* p_gw1p; cudaGetSymbolAddress((void**)&p_gw1p, d_gw1p);

    const int gNODE = NN / 8;
    const int gEDGE = (ET + 255) / 256;
    const int gHM = (NN + 63) / 64;

    k_init0<<<512, 256>>>(ei, emb0, emb1, emb2, emb3, emb4, emb5, W1, W2,
                          gw1, gb1, bng, bnb, bnm, bnv);                 // 1
    k_hist<<<(EE + 255) / 256, 256>>>(ei);                               // 2
    k_S<<<1, 256>>>(as1, ad1);                                           // 3
    k_embed<<<gNODE, 256>>>(x);                                          // 4 <- profiled
    k_scan1<<<NB, 1024>>>();                                             // 5
    k_scan23<<<NB, 1024>>>();                                            // 6
    k_scatter<<<gEDGE, 256>>>(ei);                                       // 7

    k_gat<<<gNODE, 256>>>(b1, p_o1h);                                    // 8
    k_hmma2<<<gHM, 256>>>(p_o1h, p_W2p, as2, ad2, NN);                   // 9
    k_gat<<<gNODE, 256>>>(b2, p_o2h);                                    // 10

    k_hmmaG<<<gHM, 256>>>(p_o2h, p_gw1p, gw2, gb2, batch, NN);           // 11
    k_pool<<<(NN + 127) / 128, 128>>>(batch, glw, glb, out);             // 12

    (void)in_sizes; (void)n_in; (void)out_size;
}